// round 7
// baseline (speedup 1.0000x reference)
#include <cuda_runtime.h>
#include <math.h>
#include <cstdint>

#define BATCH 2
#define SEQ   2048
#define NTOK  (BATCH*SEQ)      // 4096
#define DIM   1024
#define HEADS 16
#define HDIM  64
#define WIN   128
#define SCALE 0.125f           // 1/sqrt(64)

typedef unsigned long long u64;

// Scratch (device globals; no allocation allowed)
__device__ float g_qin[NTOK*DIM];    // rope output, tf32-rounded
__device__ float g_xr [NTOK*DIM];    // x, tf32-rounded
__device__ float g_q  [NTOK*DIM];
__device__ float g_k  [NTOK*DIM];
__device__ float g_v  [NTOK*DIM];
__device__ float g_ao [NTOK*DIM];    // attention out, tf32-rounded
__device__ float g_wr [4*DIM*DIM];   // W^T, tf32-rounded: [mat][n][k]

__device__ __forceinline__ uint32_t to_tf32(float x) {
    uint32_t u;
    asm("cvt.rna.tf32.f32 %0, %1;" : "=r"(u) : "f"(x));
    return u;
}
__device__ __forceinline__ u64 ffma2(u64 a, u64 b, u64 c) {
    u64 d;
    asm("fma.rn.f32x2 %0, %1, %2, %3;" : "=l"(d) : "l"(a), "l"(b), "l"(c));
    return d;
}

#define CPA(dst, src) \
    asm volatile("cp.async.cg.shared.global [%0], [%1], 16;" :: "r"(dst), "l"(src) : "memory")
#define CPC() asm volatile("cp.async.commit_group;" ::: "memory")
#define CPW(n) asm volatile("cp.async.wait_group %0;" :: "n"(n) : "memory")
#define LDM4(r0, r1, r2, r3, a) \
    asm volatile("ldmatrix.sync.aligned.m8n8.x4.shared.b16 {%0,%1,%2,%3}, [%4];" \
        : "=r"(r0), "=r"(r1), "=r"(r2), "=r"(r3) : "r"(a))

__device__ __forceinline__ uint32_t smem_u32(const void* p) {
    uint32_t a;
    asm("{ .reg .u64 t; cvta.to.shared.u64 t, %1; cvt.u32.u64 %0, t; }" : "=r"(a) : "l"(p));
    return a;
}

// ===========================================================================
// Prep: transpose + tf32-round all 4 weight matrices ([k][n] -> [n][k])
// ===========================================================================
__global__ void prep_w(const float* __restrict__ w0, const float* __restrict__ w1,
                       const float* __restrict__ w2, const float* __restrict__ w3) {
    __shared__ float t[32][33];
    const int z = blockIdx.z;
    const float* w = (z == 0) ? w0 : (z == 1) ? w1 : (z == 2) ? w2 : w3;
    const int k0 = blockIdx.y * 32, n0 = blockIdx.x * 32;
    for (int r = threadIdx.y; r < 32; r += 8)
        t[r][threadIdx.x] = w[(size_t)(k0 + r) * DIM + n0 + threadIdx.x];
    __syncthreads();
    float* o = g_wr + (size_t)z * DIM * DIM;
    for (int r = threadIdx.y; r < 32; r += 8)
        o[(size_t)(n0 + r) * DIM + k0 + threadIdx.x] =
            __uint_as_float(to_tf32(t[threadIdx.x][r]));
}

__global__ void prep_x(const float* __restrict__ x) {
    int i = blockIdx.x * blockDim.x + threadIdx.x;     // 1M float4
    float4 v = *(const float4*)(x + (size_t)i * 4);
    v.x = __uint_as_float(to_tf32(v.x)); v.y = __uint_as_float(to_tf32(v.y));
    v.z = __uint_as_float(to_tf32(v.z)); v.w = __uint_as_float(to_tf32(v.w));
    *(float4*)(g_xr + (size_t)i * 4) = v;
}

// ===========================================================================
// RoPE (writes tf32-rounded qin)
// ===========================================================================
__global__ void rope_kernel(const float* __restrict__ x) {
    int idx = blockIdx.x * blockDim.x + threadIdx.x;   // NTOK*512
    if (idx >= NTOK * 512) return;
    int t   = idx >> 9;
    int rem = idx & 511;
    int h   = rem >> 5;
    int i   = rem & 31;
    int s   = t & (SEQ - 1);

    float inv = expf(-(float)i * (9.210340371976184f / 32.0f));
    float ang = (float)s * inv;
    float sn, cs;
    sincosf(ang, &sn, &cs);

    const float* xp = x     + (size_t)t * DIM + h * HDIM;
    float*       qp = g_qin + (size_t)t * DIM + h * HDIM;
    float x1 = xp[i];
    float x2 = xp[i + 32];
    qp[i]      = __uint_as_float(to_tf32(x1 * cs - x2 * sn));
    qp[i + 32] = __uint_as_float(to_tf32(x2 * cs + x1 * sn));
}

// ===========================================================================
// TF32 GEMM v4: C[4096,1024] = A * W   (A rounded [m][k], Wt rounded [n][k])
// CTA 256x128, BK=32, 512 threads = 16 warps (8x2), warp tile 32x64.
// 3-stage cp.async pipeline; ldmatrix.x4 fragment loads; both smem tiles
// [rows][36] (row stride 144B -> conflict-free cp.async + ldmatrix).
// ===========================================================================
#define RSTR 36
#define A_BYTES (256 * RSTR * 4)       // 36864
#define B_BYTES (128 * RSTR * 4)       // 18432
#define SSZ     (A_BYTES + B_BYTES)    // 55296
#define GEMM_SMEM_BYTES (3 * SSZ)      // 165888
#define NCHUNK  (DIM / 32)             // 32

extern __shared__ uint32_t dsm[];

__device__ __forceinline__ void mma_tf32(float* c, const uint32_t* a, const uint32_t* b) {
    asm volatile(
        "mma.sync.aligned.m16n8k8.row.col.f32.tf32.tf32.f32 "
        "{%0,%1,%2,%3}, {%4,%5,%6,%7}, {%8,%9}, {%0,%1,%2,%3};"
        : "+f"(c[0]), "+f"(c[1]), "+f"(c[2]), "+f"(c[3])
        : "r"(a[0]), "r"(a[1]), "r"(a[2]), "r"(a[3]), "r"(b[0]), "r"(b[1]));
}

__device__ __forceinline__ void gemm_body(const float* __restrict__ A,
                                          const float* __restrict__ Wt,
                                          float* __restrict__ C,
                                          int row0, int col0) {
    const int tid  = threadIdx.x;          // 0..511
    const int wid  = tid >> 5;             // 0..15
    const int lane = tid & 31;
    const int gid  = lane >> 2;
    const int tig  = lane & 3;
    const int wm   = wid >> 1;     // 0..7  (x32 rows)
    const int wn   = wid & 1;      // 0..1  (x64 cols)
    const int mi   = lane >> 3;    // ldmatrix matrix index
    const int lr   = lane & 7;

    const uint32_t sb = smem_u32(dsm);

    // ldmatrix per-lane offsets (bytes, within a stage)
    const uint32_t a_lane = ((wm * 32 + (mi & 1) * 8 + lr) * RSTR + (mi >> 1) * 4) * 4;
    const uint32_t b_lane = ((wn * 64 + (mi >> 1) * 8 + lr) * RSTR + (mi & 1) * 4) * 4;

    float acc[2][8][4];
#pragma unroll
    for (int i = 0; i < 2; i++)
#pragma unroll
        for (int j = 0; j < 8; j++)
#pragma unroll
            for (int r = 0; r < 4; r++) acc[i][j][r] = 0.0f;

#define ISSUE_STAGE(s, c)                                                        \
    {                                                                            \
        uint32_t ab = sb + (s) * SSZ;                                            \
        _Pragma("unroll")                                                        \
        for (int it = 0; it < 4; it++) {                                         \
            int idx = it * 512 + tid;                                            \
            int m = idx >> 3, k4 = idx & 7;                                      \
            CPA(ab + m * 144 + k4 * 16,                                          \
                A + (size_t)(row0 + m) * DIM + (c) * 32 + k4 * 4);               \
        }                                                                        \
        uint32_t bb = ab + A_BYTES;                                              \
        _Pragma("unroll")                                                        \
        for (int it = 0; it < 2; it++) {                                         \
            int idx = it * 512 + tid;                                            \
            int n = idx >> 3, k4 = idx & 7;                                      \
            CPA(bb + n * 144 + k4 * 16,                                          \
                Wt + (size_t)(col0 + n) * DIM + (c) * 32 + k4 * 4);              \
        }                                                                        \
        CPC();                                                                   \
    }

    ISSUE_STAGE(0, 0);
    ISSUE_STAGE(1, 1);

    int s = 0;
    for (int c = 0; c < NCHUNK; c++) {
        CPW(1);
        __syncthreads();
        if (c + 2 < NCHUNK) {
            int sn = (s + 2 >= 3) ? s - 1 : s + 2;
            ISSUE_STAGE(sn, c + 2);
        }

        const uint32_t abase = sb + s * SSZ;
        const uint32_t bbase = abase + A_BYTES;
#pragma unroll
        for (int ss = 0; ss < 4; ss++) {
            const int ksf = ss * 8 * 4;          // byte offset of k substep
            uint32_t af[2][4], bf[8][2];
#pragma unroll
            for (int i = 0; i < 2; i++)
                LDM4(af[i][0], af[i][1], af[i][2], af[i][3],
                     abase + a_lane + i * (16 * RSTR * 4) + ksf);
#pragma unroll
            for (int jj = 0; jj < 4; jj++)
                LDM4(bf[2 * jj][0], bf[2 * jj][1], bf[2 * jj + 1][0], bf[2 * jj + 1][1],
                     bbase + b_lane + jj * (16 * RSTR * 4) + ksf);
#pragma unroll
            for (int i = 0; i < 2; i++)
#pragma unroll
                for (int j = 0; j < 8; j++)
                    mma_tf32(acc[i][j], af[i], bf[j]);
        }
        s = (s + 1 == 3) ? 0 : s + 1;
    }

    // Epilogue
#pragma unroll
    for (int i = 0; i < 2; i++) {
        int r0 = row0 + wm * 32 + i * 16 + gid;
#pragma unroll
        for (int j = 0; j < 8; j++) {
            int cc = col0 + wn * 64 + j * 8 + tig * 2;
            *(float2*)(C + (size_t)r0 * DIM + cc)       = make_float2(acc[i][j][0], acc[i][j][1]);
            *(float2*)(C + (size_t)(r0 + 8) * DIM + cc) = make_float2(acc[i][j][2], acc[i][j][3]);
        }
    }
}

__global__ __launch_bounds__(512)
void gemm_qkv() {
    const int mi   = blockIdx.x >> 3;            // 0=Q 1=K 2=V
    const int col0 = (blockIdx.x & 7) * 128;
    const int row0 = blockIdx.y * 256;
    const float* A  = (mi < 2) ? g_qin : g_xr;
    float*       C  = (mi == 0) ? g_q : (mi == 1) ? g_k : g_v;
    const float* Wt = g_wr + (size_t)mi * DIM * DIM;
    gemm_body(A, Wt, C, row0, col0);
}

__global__ __launch_bounds__(512)
void gemm_out(float* __restrict__ out) {
    const int col0 = blockIdx.x * 128;
    const int row0 = blockIdx.y * 256;
    gemm_body(g_ao, g_wr + (size_t)3 * DIM * DIM, out, row0, col0);
}

// ===========================================================================
// Sliding-window attention, f32x2 FFMA with 4 independent dot chains and
// LDS.128 row loads. One thread per query row.
// ===========================================================================
extern __shared__ float sh_attn[];   // Ks[128*64] then Vs[128*64]

__global__ __launch_bounds__(128)
void attn_kernel() {
    float* Ks = sh_attn;
    float* Vs = sh_attn + 128 * 64;

    const int qt  = blockIdx.x;
    const int h   = blockIdx.y;
    const int b   = blockIdx.z;
    const int tid = threadIdx.x;
    const int qi  = qt * 128 + tid;

    const float* qp = g_q + (size_t)(b * SEQ + qi) * DIM + h * HDIM;
    u64 q2[32];
#pragma unroll
    for (int d = 0; d < 16; d++) {
        float4 v4 = *(const float4*)(qp + d * 4);
        q2[d * 2]     = *(const u64*)&v4.x;
        q2[d * 2 + 1] = *(const u64*)&v4.z;
    }

    u64 acc2[32];
#pragma unroll
    for (int d = 0; d < 32; d++) acc2[d] = 0ULL;
    float l = 0.0f;

    const int ntiles = SEQ / 128;
    for (int pass = 0; pass < 3; pass++) {
        const int kt = qt - 1 + pass;
        if (kt < 0 || kt >= ntiles) continue;

        __syncthreads();
        const float* kb = g_k + (size_t)(b * SEQ + kt * 128) * DIM + h * HDIM;
        const float* vb = g_v + (size_t)(b * SEQ + kt * 128) * DIM + h * HDIM;
#pragma unroll
        for (int i = 0; i < 16; i++) {
            int idx = i * 128 + tid;
            int r   = idx >> 4;
            int d4  = (idx & 15) << 2;
            *(float4*)&Ks[r * 64 + d4] = *(const float4*)(kb + (size_t)r * DIM + d4);
            *(float4*)&Vs[r * 64 + d4] = *(const float4*)(vb + (size_t)r * DIM + d4);
        }
        __syncthreads();

        const int rlo = (pass == 0) ? 1 : 0;
        const int rhi = (pass == 2) ? 127 : 128;
        for (int r = rlo; r < rhi; r++) {
            bool valid = (pass == 1) || (pass == 0 ? (r > tid) : (r < tid));
            if (valid) {
                const float4* kr4 = (const float4*)&Ks[r * 64];
                u64 s[4] = {0ULL, 0ULL, 0ULL, 0ULL};
#pragma unroll
                for (int dd = 0; dd < 16; dd++) {
                    float4 kv = kr4[dd];
                    s[dd & 3] = ffma2(q2[2 * dd],     *(u64*)&kv.x, s[dd & 3]);
                    s[dd & 3] = ffma2(q2[2 * dd + 1], *(u64*)&kv.z, s[dd & 3]);
                }
                float2 f0 = *(float2*)&s[0], f1 = *(float2*)&s[1];
                float2 f2 = *(float2*)&s[2], f3 = *(float2*)&s[3];
                float dot = ((f0.x + f0.y) + (f1.x + f1.y)) +
                            ((f2.x + f2.y) + (f3.x + f3.y));
                float p = __expf(dot * SCALE);
                l += p;
                float2 pp = make_float2(p, p);
                u64 p2 = *(u64*)&pp;
                const float4* vr4 = (const float4*)&Vs[r * 64];
#pragma unroll
                for (int dd = 0; dd < 16; dd++) {
                    float4 vv = vr4[dd];
                    acc2[2 * dd]     = ffma2(p2, *(u64*)&vv.x, acc2[2 * dd]);
                    acc2[2 * dd + 1] = ffma2(p2, *(u64*)&vv.z, acc2[2 * dd + 1]);
                }
            }
        }
    }

    const float inv = 1.0f / l;
    float* op = g_ao + (size_t)(b * SEQ + qi) * DIM + h * HDIM;
#pragma unroll
    for (int d = 0; d < 32; d++) {
        float2 a = *(float2*)&acc2[d];
        *(float2*)(op + d * 2) = make_float2(__uint_as_float(to_tf32(a.x * inv)),
                                             __uint_as_float(to_tf32(a.y * inv)));
    }
}

// ===========================================================================
extern "C" void kernel_launch(void* const* d_in, const int* in_sizes, int n_in,
                              void* d_out, int out_size) {
    const float* x  = (const float*)d_in[0];
    const float* Wq = (const float*)d_in[1];
    const float* Wk = (const float*)d_in[2];
    const float* Wv = (const float*)d_in[3];
    const float* Wo = (const float*)d_in[4];
    float* out = (float*)d_out;

    cudaFuncSetAttribute(attn_kernel,
                         cudaFuncAttributeMaxDynamicSharedMemorySize, 65536);
    cudaFuncSetAttribute(gemm_qkv,
                         cudaFuncAttributeMaxDynamicSharedMemorySize, GEMM_SMEM_BYTES);
    cudaFuncSetAttribute(gemm_out,
                         cudaFuncAttributeMaxDynamicSharedMemorySize, GEMM_SMEM_BYTES);

    // 0. Prep: round+transpose weights, round x
    prep_w<<<dim3(32, 32, 4), dim3(32, 8)>>>(Wq, Wk, Wv, Wo);
    prep_x<<<4096, 256>>>(x);

    // 1. RoPE (rounded qin)
    rope_kernel<<<(NTOK * 512 + 255) / 256, 256>>>(x);

    // 2. Q,K,V projections in one launch
    gemm_qkv<<<dim3(24, 16), 512, GEMM_SMEM_BYTES>>>();

    // 3. Windowed attention
    attn_kernel<<<dim3(SEQ / 128, HEADS, BATCH), 128, 65536>>>();

    // 4. Output projection -> d_out
    gemm_out<<<dim3(8, 16), 512, GEMM_SMEM_BYTES>>>(out);
    (void)in_sizes; (void)n_in; (void)out_size;
}

// round 8
// speedup vs baseline: 1.5306x; 1.5306x over previous
#include <cuda_runtime.h>
#include <math.h>
#include <cstdint>

#define BATCH 2
#define SEQ   2048
#define NTOK  (BATCH*SEQ)      // 4096
#define DIM   1024
#define HEADS 16
#define HDIM  64
#define WIN   128
#define SCALE 0.125f           // 1/sqrt(64)

typedef unsigned long long u64;

// Scratch (device globals; no allocation allowed)
__device__ float g_qin[NTOK*DIM];    // rope output, tf32-rounded
__device__ float g_xr [NTOK*DIM];    // x, tf32-rounded
__device__ float g_q  [NTOK*DIM];    // Q, tf32-rounded (gemm epilogue)
__device__ float g_k  [NTOK*DIM];    // K, tf32-rounded
__device__ float g_vt [NTOK*DIM];    // V^T, tf32-rounded: [(b*16+h)*64+d][s]
__device__ float g_ao [NTOK*DIM];    // attention out, tf32-rounded
__device__ float g_wr [4*DIM*DIM];   // W^T, tf32-rounded: [mat][n][k]

__device__ __forceinline__ uint32_t to_tf32(float x) {
    uint32_t u;
    asm("cvt.rna.tf32.f32 %0, %1;" : "=r"(u) : "f"(x));
    return u;
}
__device__ __forceinline__ float to_tf32f(float x) { return __uint_as_float(to_tf32(x)); }

#define CPA(dst, src) \
    asm volatile("cp.async.cg.shared.global [%0], [%1], 16;" :: "r"(dst), "l"(src) : "memory")
#define CPC() asm volatile("cp.async.commit_group;" ::: "memory")
#define CPW(n) asm volatile("cp.async.wait_group %0;" :: "n"(n) : "memory")
#define LDM4(r0, r1, r2, r3, a) \
    asm volatile("ldmatrix.sync.aligned.m8n8.x4.shared.b16 {%0,%1,%2,%3}, [%4];" \
        : "=r"(r0), "=r"(r1), "=r"(r2), "=r"(r3) : "r"(a))

__device__ __forceinline__ uint32_t smem_u32(const void* p) {
    uint32_t a;
    asm("{ .reg .u64 t; cvta.to.shared.u64 t, %1; cvt.u32.u64 %0, t; }" : "=r"(a) : "l"(p));
    return a;
}

__device__ __forceinline__ void mma_tf32(float* c, const uint32_t* a, const uint32_t* b) {
    asm volatile(
        "mma.sync.aligned.m16n8k8.row.col.f32.tf32.tf32.f32 "
        "{%0,%1,%2,%3}, {%4,%5,%6,%7}, {%8,%9}, {%0,%1,%2,%3};"
        : "+f"(c[0]), "+f"(c[1]), "+f"(c[2]), "+f"(c[3])
        : "r"(a[0]), "r"(a[1]), "r"(a[2]), "r"(a[3]), "r"(b[0]), "r"(b[1]));
}

// ===========================================================================
// Prep: transpose + tf32-round all 4 weight matrices ([k][n] -> [n][k])
// ===========================================================================
__global__ void prep_w(const float* __restrict__ w0, const float* __restrict__ w1,
                       const float* __restrict__ w2, const float* __restrict__ w3) {
    __shared__ float t[32][33];
    const int z = blockIdx.z;
    const float* w = (z == 0) ? w0 : (z == 1) ? w1 : (z == 2) ? w2 : w3;
    const int k0 = blockIdx.y * 32, n0 = blockIdx.x * 32;
    for (int r = threadIdx.y; r < 32; r += 8)
        t[r][threadIdx.x] = w[(size_t)(k0 + r) * DIM + n0 + threadIdx.x];
    __syncthreads();
    float* o = g_wr + (size_t)z * DIM * DIM;
    for (int r = threadIdx.y; r < 32; r += 8)
        o[(size_t)(n0 + r) * DIM + k0 + threadIdx.x] = to_tf32f(t[threadIdx.x][r]);
}

__global__ void prep_x(const float* __restrict__ x) {
    int i = blockIdx.x * blockDim.x + threadIdx.x;     // 1M float4
    float4 v = *(const float4*)(x + (size_t)i * 4);
    v.x = to_tf32f(v.x); v.y = to_tf32f(v.y);
    v.z = to_tf32f(v.z); v.w = to_tf32f(v.w);
    *(float4*)(g_xr + (size_t)i * 4) = v;
}

// ===========================================================================
// RoPE (writes tf32-rounded qin)
// ===========================================================================
__global__ void rope_kernel(const float* __restrict__ x) {
    int idx = blockIdx.x * blockDim.x + threadIdx.x;   // NTOK*512
    if (idx >= NTOK * 512) return;
    int t   = idx >> 9;
    int rem = idx & 511;
    int h   = rem >> 5;
    int i   = rem & 31;
    int s   = t & (SEQ - 1);

    float inv = expf(-(float)i * (9.210340371976184f / 32.0f));
    float ang = (float)s * inv;
    float sn, cs;
    sincosf(ang, &sn, &cs);

    const float* xp = x     + (size_t)t * DIM + h * HDIM;
    float*       qp = g_qin + (size_t)t * DIM + h * HDIM;
    float x1 = xp[i];
    float x2 = xp[i + 32];
    qp[i]      = to_tf32f(x1 * cs - x2 * sn);
    qp[i + 32] = to_tf32f(x2 * cs + x1 * sn);
}

// ===========================================================================
// TF32 GEMM (round-6 config: 256 thr, CTA 256x128, warp tile 64x64, BK=32,
// 3-stage cp.async, ldmatrix). Templated epilogue:
//   MODE 0: plain fp32 store        (output projection)
//   MODE 1: tf32-rounded store      (Q, K)
//   MODE 2: tf32-rounded TRANSPOSED store into g_vt  (V)
// ===========================================================================
#define RSTR 36
#define A_BYTES (256 * RSTR * 4)       // 36864
#define B_BYTES (128 * RSTR * 4)       // 18432
#define SSZ     (A_BYTES + B_BYTES)    // 55296
#define GEMM_SMEM_BYTES (3 * SSZ)      // 165888
#define NCHUNK  (DIM / 32)             // 32

extern __shared__ uint32_t dsm[];

template <int MODE>
__device__ __forceinline__ void gemm_body(const float* __restrict__ A,
                                          const float* __restrict__ Wt,
                                          float* __restrict__ C,
                                          int row0, int col0) {
    const int tid  = threadIdx.x;
    const int wid  = tid >> 5;
    const int lane = tid & 31;
    const int gid  = lane >> 2;
    const int tig  = lane & 3;
    const int wm   = wid >> 1;     // 0..3
    const int wn   = wid & 1;      // 0..1
    const int mi   = lane >> 3;
    const int lr   = lane & 7;

    const uint32_t sb = smem_u32(dsm);

    const uint32_t a_lane = ((wm * 64 + (mi & 1) * 8 + lr) * RSTR + (mi >> 1) * 4) * 4;
    const uint32_t b_lane = ((wn * 64 + (mi >> 1) * 8 + lr) * RSTR + (mi & 1) * 4) * 4;

    float acc[4][8][4];
#pragma unroll
    for (int i = 0; i < 4; i++)
#pragma unroll
        for (int j = 0; j < 8; j++)
#pragma unroll
            for (int r = 0; r < 4; r++) acc[i][j][r] = 0.0f;

#define ISSUE_STAGE(s, c)                                                        \
    {                                                                            \
        uint32_t ab = sb + (s) * SSZ;                                            \
        _Pragma("unroll")                                                        \
        for (int it = 0; it < 8; it++) {                                         \
            int idx = it * 256 + tid;                                            \
            int m = idx >> 3, k4 = idx & 7;                                      \
            CPA(ab + m * 144 + k4 * 16,                                          \
                A + (size_t)(row0 + m) * DIM + (c) * 32 + k4 * 4);               \
        }                                                                        \
        uint32_t bb = ab + A_BYTES;                                              \
        _Pragma("unroll")                                                        \
        for (int it = 0; it < 4; it++) {                                         \
            int idx = it * 256 + tid;                                            \
            int n = idx >> 3, k4 = idx & 7;                                      \
            CPA(bb + n * 144 + k4 * 16,                                          \
                Wt + (size_t)(col0 + n) * DIM + (c) * 32 + k4 * 4);              \
        }                                                                        \
        CPC();                                                                   \
    }

    ISSUE_STAGE(0, 0);
    ISSUE_STAGE(1, 1);

    int s = 0;
    for (int c = 0; c < NCHUNK; c++) {
        CPW(1);
        __syncthreads();
        if (c + 2 < NCHUNK) {
            int sn = (s + 2 >= 3) ? s - 1 : s + 2;
            ISSUE_STAGE(sn, c + 2);
        }

        const uint32_t abase = sb + s * SSZ;
        const uint32_t bbase = abase + A_BYTES;
#pragma unroll
        for (int ss = 0; ss < 4; ss++) {
            const int ksf = ss * 8 * 4;
            uint32_t af[4][4], bf[8][2];
#pragma unroll
            for (int i = 0; i < 4; i++)
                LDM4(af[i][0], af[i][1], af[i][2], af[i][3],
                     abase + a_lane + i * (16 * RSTR * 4) + ksf);
#pragma unroll
            for (int jj = 0; jj < 4; jj++)
                LDM4(bf[2 * jj][0], bf[2 * jj][1], bf[2 * jj + 1][0], bf[2 * jj + 1][1],
                     bbase + b_lane + jj * (16 * RSTR * 4) + ksf);
#pragma unroll
            for (int i = 0; i < 4; i++)
#pragma unroll
                for (int j = 0; j < 8; j++)
                    mma_tf32(acc[i][j], af[i], bf[j]);
        }
        s = (s + 1 == 3) ? 0 : s + 1;
    }

    // Epilogue
#pragma unroll
    for (int i = 0; i < 4; i++) {
        int r0 = row0 + wm * 64 + i * 16 + gid;
#pragma unroll
        for (int j = 0; j < 8; j++) {
            int cc = col0 + wn * 64 + j * 8 + tig * 2;
            if (MODE == 0) {
                *(float2*)(C + (size_t)r0 * DIM + cc)       = make_float2(acc[i][j][0], acc[i][j][1]);
                *(float2*)(C + (size_t)(r0 + 8) * DIM + cc) = make_float2(acc[i][j][2], acc[i][j][3]);
            } else if (MODE == 1) {
                *(float2*)(C + (size_t)r0 * DIM + cc) =
                    make_float2(to_tf32f(acc[i][j][0]), to_tf32f(acc[i][j][1]));
                *(float2*)(C + (size_t)(r0 + 8) * DIM + cc) =
                    make_float2(to_tf32f(acc[i][j][2]), to_tf32f(acc[i][j][3]));
            } else {
                // transposed: g_vt[((b*16+h)*64+d)*SEQ + s], t=row, cc=h*64+d
                int b0 = r0 >> 11, s0 = r0 & 2047;
                int hh = cc >> 6,  dd = cc & 63;
                float* base = C + ((size_t)(b0 * HEADS + hh) * HDIM) * SEQ;
                base[(size_t)(dd)     * SEQ + s0] = to_tf32f(acc[i][j][0]);
                base[(size_t)(dd + 1) * SEQ + s0] = to_tf32f(acc[i][j][1]);
                int r1 = r0 + 8;
                int b1 = r1 >> 11, s1 = r1 & 2047;
                float* base1 = C + ((size_t)(b1 * HEADS + hh) * HDIM) * SEQ;
                base1[(size_t)(dd)     * SEQ + s1] = to_tf32f(acc[i][j][2]);
                base1[(size_t)(dd + 1) * SEQ + s1] = to_tf32f(acc[i][j][3]);
            }
        }
    }
}

__global__ __launch_bounds__(256)
void gemm_qkv() {
    const int mi   = blockIdx.x >> 3;            // 0=Q 1=K 2=V
    const int col0 = (blockIdx.x & 7) * 128;
    const int row0 = blockIdx.y * 256;
    const float* Wt = g_wr + (size_t)mi * DIM * DIM;
    if (mi == 0)      gemm_body<1>(g_qin, Wt, g_q,  row0, col0);
    else if (mi == 1) gemm_body<1>(g_qin, Wt, g_k,  row0, col0);
    else              gemm_body<2>(g_xr,  Wt, g_vt, row0, col0);
}

__global__ __launch_bounds__(256)
void gemm_out(float* __restrict__ out) {
    gemm_body<0>(g_ao, g_wr + (size_t)3 * DIM * DIM, out, blockIdx.y * 256, blockIdx.x * 128);
}

// ===========================================================================
// MMA attention: CTA = (128-q tile, head, batch), 8 warps, 64-key passes.
// Warp w owns q rows [16w,16w+16). Per pass: S = Q K^T (MMA), mask+exp,
// P -> warp-private smem slab, O += P V (MMA, V^T precomputed in gemm).
// smem (floats, stride 68 = 17x16B, conflict-free ldmatrix):
//   Qs[128*68] | Ks[64*68] | Vt[64*68] | Ps[128*68]
// ===========================================================================
#define AST 68
#define ATTN_SMEM_BYTES ((128*AST + 64*AST + 64*AST + 128*AST) * 4)  // 104448

__global__ __launch_bounds__(256)
void attn_mma() {
    extern __shared__ float afm[];
    float* Ps_f = afm + 128 * AST + 64 * AST + 64 * AST;

    const int tid  = threadIdx.x;
    const int wid  = tid >> 5;
    const int lane = tid & 31;
    const int gid  = lane >> 2;
    const int tig  = lane & 3;
    const int mi   = lane >> 3;
    const int lr   = lane & 7;

    const int qt = blockIdx.x, h = blockIdx.y, b = blockIdx.z;
    const int q0 = qt * 128;

    const uint32_t sb = smem_u32(afm);
    const uint32_t Qb = sb;
    const uint32_t Kb = sb + 128 * AST * 4;
    const uint32_t Vb = Kb + 64 * AST * 4;
    const uint32_t Pb = Vb + 64 * AST * 4;

    // Load Q tile once (128 x 64), already tf32-rounded
    const float* Qg = g_q + ((size_t)(b * SEQ + q0)) * DIM + h * HDIM;
#pragma unroll
    for (int it = 0; it < 8; it++) {
        int idx = it * 256 + tid;          // 0..2047 float4 slots
        int r = idx >> 4, c4 = idx & 15;
        CPA(Qb + (r * AST + c4 * 4) * 4, Qg + (size_t)r * DIM + c4 * 4);
    }
    CPC();

    const uint32_t a_q = Qb + ((16 * wid + (mi & 1) * 8 + lr) * AST + (mi >> 1) * 4) * 4;
    const uint32_t a_p = Pb + (16 * wid) * AST * 4 + (((mi & 1) * 8 + lr) * AST + (mi >> 1) * 4) * 4;
    const uint32_t boff = ((mi >> 1) * 8 + lr) * AST * 4 + (mi & 1) * 16;

    float o[8][4];
#pragma unroll
    for (int j = 0; j < 8; j++)
#pragma unroll
        for (int r = 0; r < 4; r++) o[j][r] = 0.0f;
    float lp0 = 0.0f, lp1 = 0.0f;
    const int r0g = q0 + 16 * wid + gid;

    for (int p6 = 0; p6 < 6; p6++) {
        const int kt0 = q0 - 128 + p6 * 64;
        if (kt0 < 0 || kt0 >= SEQ) continue;

        __syncthreads();   // previous pass fully consumed K/V
        const float* Kg = g_k  + ((size_t)(b * SEQ + kt0)) * DIM + h * HDIM;
        const float* Vg = g_vt + ((size_t)((b * HEADS + h) * HDIM)) * SEQ + kt0;
#pragma unroll
        for (int it = 0; it < 4; it++) {
            int idx = it * 256 + tid;      // 0..1023 float4 slots
            int r = idx >> 4, c4 = idx & 15;
            CPA(Kb + (r * AST + c4 * 4) * 4, Kg + (size_t)r * DIM + c4 * 4);
            CPA(Vb + (r * AST + c4 * 4) * 4, Vg + (size_t)r * SEQ + c4 * 4);
        }
        CPC(); CPW(0);
        __syncthreads();

        // warp relevance: any key in this pass within window of warp's rows?
        if (kt0 + 63 >= q0 + 16 * wid - 127 && kt0 <= q0 + 16 * wid + 15 + 127) {
            // ---- S = Q K^T ----
            float sc[8][4];
#pragma unroll
            for (int j = 0; j < 8; j++)
#pragma unroll
                for (int r = 0; r < 4; r++) sc[j][r] = 0.0f;
#pragma unroll
            for (int ss = 0; ss < 8; ss++) {
                uint32_t aq[4], bf[8][2];
                LDM4(aq[0], aq[1], aq[2], aq[3], a_q + ss * 32);
#pragma unroll
                for (int jj = 0; jj < 4; jj++)
                    LDM4(bf[2*jj][0], bf[2*jj][1], bf[2*jj+1][0], bf[2*jj+1][1],
                         Kb + jj * (16 * AST * 4) + boff + ss * 32);
#pragma unroll
                for (int j = 0; j < 8; j++) mma_tf32(sc[j], aq, bf[j]);
            }
            // ---- mask + exp + P store ----
#pragma unroll
            for (int j = 0; j < 8; j++) {
                int col = kt0 + j * 8 + 2 * tig;
                float e0 = (abs(r0g - col)     < WIN) ? __expf(sc[j][0] * SCALE) : 0.0f;
                float e1 = (abs(r0g - col - 1) < WIN) ? __expf(sc[j][1] * SCALE) : 0.0f;
                float e2 = (abs(r0g + 8 - col)     < WIN) ? __expf(sc[j][2] * SCALE) : 0.0f;
                float e3 = (abs(r0g + 8 - col - 1) < WIN) ? __expf(sc[j][3] * SCALE) : 0.0f;
                e0 = to_tf32f(e0); e1 = to_tf32f(e1);
                e2 = to_tf32f(e2); e3 = to_tf32f(e3);
                lp0 += e0 + e1;
                lp1 += e2 + e3;
                float* p0 = Ps_f + (16 * wid + gid) * AST + j * 8 + 2 * tig;
                float* p1 = Ps_f + (16 * wid + gid + 8) * AST + j * 8 + 2 * tig;
                *(float2*)p0 = make_float2(e0, e1);
                *(float2*)p1 = make_float2(e2, e3);
            }
            __syncwarp();
            // ---- O += P V ----
#pragma unroll
            for (int ss = 0; ss < 8; ss++) {
                uint32_t ap[4], bf[8][2];
                LDM4(ap[0], ap[1], ap[2], ap[3], a_p + ss * 32);
#pragma unroll
                for (int jj = 0; jj < 4; jj++)
                    LDM4(bf[2*jj][0], bf[2*jj][1], bf[2*jj+1][0], bf[2*jj+1][1],
                         Vb + jj * (16 * AST * 4) + boff + ss * 32);
#pragma unroll
                for (int j = 0; j < 8; j++) mma_tf32(o[j], ap, bf[j]);
            }
        }
    }

    // row-sum l across the tig quad
    lp0 += __shfl_xor_sync(0xffffffff, lp0, 1);
    lp0 += __shfl_xor_sync(0xffffffff, lp0, 2);
    lp1 += __shfl_xor_sync(0xffffffff, lp1, 1);
    lp1 += __shfl_xor_sync(0xffffffff, lp1, 2);
    const float inv0 = 1.0f / lp0;
    const float inv1 = 1.0f / lp1;

    float* Og = g_ao + ((size_t)(b * SEQ + r0g)) * DIM + h * HDIM;
#pragma unroll
    for (int j = 0; j < 8; j++) {
        int c = j * 8 + 2 * tig;
        *(float2*)(Og + c) =
            make_float2(to_tf32f(o[j][0] * inv0), to_tf32f(o[j][1] * inv0));
        *(float2*)(Og + (size_t)8 * DIM + c) =
            make_float2(to_tf32f(o[j][2] * inv1), to_tf32f(o[j][3] * inv1));
    }
}

// ===========================================================================
extern "C" void kernel_launch(void* const* d_in, const int* in_sizes, int n_in,
                              void* d_out, int out_size) {
    const float* x  = (const float*)d_in[0];
    const float* Wq = (const float*)d_in[1];
    const float* Wk = (const float*)d_in[2];
    const float* Wv = (const float*)d_in[3];
    const float* Wo = (const float*)d_in[4];
    float* out = (float*)d_out;

    cudaFuncSetAttribute(gemm_qkv,
                         cudaFuncAttributeMaxDynamicSharedMemorySize, GEMM_SMEM_BYTES);
    cudaFuncSetAttribute(gemm_out,
                         cudaFuncAttributeMaxDynamicSharedMemorySize, GEMM_SMEM_BYTES);
    cudaFuncSetAttribute(attn_mma,
                         cudaFuncAttributeMaxDynamicSharedMemorySize, ATTN_SMEM_BYTES);

    // 0. Prep
    prep_w<<<dim3(32, 32, 4), dim3(32, 8)>>>(Wq, Wk, Wv, Wo);
    prep_x<<<4096, 256>>>(x);

    // 1. RoPE
    rope_kernel<<<(NTOK * 512 + 255) / 256, 256>>>(x);

    // 2. Q,K,V projections (V written transposed + all rounded)
    gemm_qkv<<<dim3(24, 16), 256, GEMM_SMEM_BYTES>>>();

    // 3. MMA windowed attention
    attn_mma<<<dim3(SEQ / 128, HEADS, BATCH), 256, ATTN_SMEM_BYTES>>>();

    // 4. Output projection -> d_out
    gemm_out<<<dim3(8, 16), 256, GEMM_SMEM_BYTES>>>(out);
    (void)in_sizes; (void)n_in; (void)out_size;
}

// round 9
// speedup vs baseline: 1.5933x; 1.0410x over previous
#include <cuda_runtime.h>
#include <math.h>
#include <cstdint>

#define BATCH 2
#define SEQ   2048
#define NTOK  (BATCH*SEQ)      // 4096
#define DIM   1024
#define HEADS 16
#define HDIM  64
#define WIN   128
#define SCALE 0.125f           // 1/sqrt(64)

typedef unsigned long long u64;

// Scratch (device globals; no allocation allowed)
__device__ float g_qin[NTOK*DIM];    // rope output, tf32-rounded
__device__ float g_xr [NTOK*DIM];    // x, tf32-rounded
__device__ float g_q  [NTOK*DIM];    // Q, tf32-rounded (gemm epilogue)
__device__ float g_k  [NTOK*DIM];    // K, tf32-rounded
__device__ float g_vt [NTOK*DIM];    // V^T, tf32-rounded: [(b*16+h)*64+d][s]
__device__ float g_ao [NTOK*DIM];    // attention out, tf32-rounded
__device__ float g_wr [4*DIM*DIM];   // W^T, tf32-rounded: [mat][n][k]

__device__ __forceinline__ uint32_t to_tf32(float x) {
    uint32_t u;
    asm("cvt.rna.tf32.f32 %0, %1;" : "=r"(u) : "f"(x));
    return u;
}
__device__ __forceinline__ float to_tf32f(float x) { return __uint_as_float(to_tf32(x)); }

#define CPA(dst, src) \
    asm volatile("cp.async.cg.shared.global [%0], [%1], 16;" :: "r"(dst), "l"(src) : "memory")
#define CPC() asm volatile("cp.async.commit_group;" ::: "memory")
#define CPW(n) asm volatile("cp.async.wait_group %0;" :: "n"(n) : "memory")
#define LDM4(r0, r1, r2, r3, a) \
    asm volatile("ldmatrix.sync.aligned.m8n8.x4.shared.b16 {%0,%1,%2,%3}, [%4];" \
        : "=r"(r0), "=r"(r1), "=r"(r2), "=r"(r3) : "r"(a))

__device__ __forceinline__ uint32_t smem_u32(const void* p) {
    uint32_t a;
    asm("{ .reg .u64 t; cvta.to.shared.u64 t, %1; cvt.u32.u64 %0, t; }" : "=r"(a) : "l"(p));
    return a;
}

__device__ __forceinline__ void mma_tf32(float* c, const uint32_t* a, const uint32_t* b) {
    asm volatile(
        "mma.sync.aligned.m16n8k8.row.col.f32.tf32.tf32.f32 "
        "{%0,%1,%2,%3}, {%4,%5,%6,%7}, {%8,%9}, {%0,%1,%2,%3};"
        : "+f"(c[0]), "+f"(c[1]), "+f"(c[2]), "+f"(c[3])
        : "r"(a[0]), "r"(a[1]), "r"(a[2]), "r"(a[3]), "r"(b[0]), "r"(b[1]));
}

// ===========================================================================
// Prep: transpose + tf32-round all 4 weight matrices ([k][n] -> [n][k])
// ===========================================================================
__global__ void prep_w(const float* __restrict__ w0, const float* __restrict__ w1,
                       const float* __restrict__ w2, const float* __restrict__ w3) {
    __shared__ float t[32][33];
    const int z = blockIdx.z;
    const float* w = (z == 0) ? w0 : (z == 1) ? w1 : (z == 2) ? w2 : w3;
    const int k0 = blockIdx.y * 32, n0 = blockIdx.x * 32;
    for (int r = threadIdx.y; r < 32; r += 8)
        t[r][threadIdx.x] = w[(size_t)(k0 + r) * DIM + n0 + threadIdx.x];
    __syncthreads();
    float* o = g_wr + (size_t)z * DIM * DIM;
    for (int r = threadIdx.y; r < 32; r += 8)
        o[(size_t)(n0 + r) * DIM + k0 + threadIdx.x] = to_tf32f(t[threadIdx.x][r]);
}

__global__ void prep_x(const float* __restrict__ x) {
    int i = blockIdx.x * blockDim.x + threadIdx.x;     // 1M float4
    float4 v = *(const float4*)(x + (size_t)i * 4);
    v.x = to_tf32f(v.x); v.y = to_tf32f(v.y);
    v.z = to_tf32f(v.z); v.w = to_tf32f(v.w);
    *(float4*)(g_xr + (size_t)i * 4) = v;
}

// ===========================================================================
// RoPE (writes tf32-rounded qin)
// ===========================================================================
__global__ void rope_kernel(const float* __restrict__ x) {
    int idx = blockIdx.x * blockDim.x + threadIdx.x;   // NTOK*512
    if (idx >= NTOK * 512) return;
    int t   = idx >> 9;
    int rem = idx & 511;
    int h   = rem >> 5;
    int i   = rem & 31;
    int s   = t & (SEQ - 1);

    float inv = expf(-(float)i * (9.210340371976184f / 32.0f));
    float ang = (float)s * inv;
    float sn, cs;
    sincosf(ang, &sn, &cs);

    const float* xp = x     + (size_t)t * DIM + h * HDIM;
    float*       qp = g_qin + (size_t)t * DIM + h * HDIM;
    float x1 = xp[i];
    float x2 = xp[i + 32];
    qp[i]      = to_tf32f(x1 * cs - x2 * sn);
    qp[i + 32] = to_tf32f(x2 * cs + x1 * sn);
}

// ===========================================================================
// TF32 GEMM v5: CTA 128x128, 256 thr, 8 warps (4x2), warp tile 32x64, BK=32,
// 3-stage cp.async, ldmatrix; 110.6KB smem -> 2 CTAs/SM (launch_bounds 256,2).
// Templated epilogue: 0=plain, 1=tf32-rounded, 2=rounded transposed (V).
// ===========================================================================
#define RSTR 36
#define A_BYTES (128 * RSTR * 4)       // 18432
#define B_BYTES (128 * RSTR * 4)       // 18432
#define SSZ     (A_BYTES + B_BYTES)    // 36864
#define GEMM_SMEM_BYTES (3 * SSZ)      // 110592
#define NCHUNK  (DIM / 32)             // 32

extern __shared__ uint32_t dsm[];

template <int MODE>
__device__ __forceinline__ void gemm_body(const float* __restrict__ A,
                                          const float* __restrict__ Wt,
                                          float* __restrict__ C,
                                          int row0, int col0) {
    const int tid  = threadIdx.x;      // 0..255
    const int wid  = tid >> 5;         // 0..7
    const int lane = tid & 31;
    const int gid  = lane >> 2;
    const int tig  = lane & 3;
    const int wm   = wid >> 1;     // 0..3  (x32 rows)
    const int wn   = wid & 1;      // 0..1  (x64 cols)
    const int mi   = lane >> 3;
    const int lr   = lane & 7;

    const uint32_t sb = smem_u32(dsm);

    const uint32_t a_lane = ((wm * 32 + (mi & 1) * 8 + lr) * RSTR + (mi >> 1) * 4) * 4;
    const uint32_t b_lane = ((wn * 64 + (mi >> 1) * 8 + lr) * RSTR + (mi & 1) * 4) * 4;

    float acc[2][8][4];
#pragma unroll
    for (int i = 0; i < 2; i++)
#pragma unroll
        for (int j = 0; j < 8; j++)
#pragma unroll
            for (int r = 0; r < 4; r++) acc[i][j][r] = 0.0f;

    // A and B tiles are both 128 rows x 8 float4: 1024 slots, 4/thread each.
#define ISSUE_STAGE(s, c)                                                        \
    {                                                                            \
        uint32_t ab = sb + (s) * SSZ;                                            \
        uint32_t bb = ab + A_BYTES;                                              \
        _Pragma("unroll")                                                        \
        for (int it = 0; it < 4; it++) {                                         \
            int idx = it * 256 + tid;                                            \
            int m = idx >> 3, k4 = idx & 7;                                      \
            CPA(ab + m * 144 + k4 * 16,                                          \
                A + (size_t)(row0 + m) * DIM + (c) * 32 + k4 * 4);               \
            CPA(bb + m * 144 + k4 * 16,                                          \
                Wt + (size_t)(col0 + m) * DIM + (c) * 32 + k4 * 4);              \
        }                                                                        \
        CPC();                                                                   \
    }

    ISSUE_STAGE(0, 0);
    ISSUE_STAGE(1, 1);

    int s = 0;
    for (int c = 0; c < NCHUNK; c++) {
        CPW(1);
        __syncthreads();
        if (c + 2 < NCHUNK) {
            int sn = (s + 2 >= 3) ? s - 1 : s + 2;
            ISSUE_STAGE(sn, c + 2);
        }

        const uint32_t abase = sb + s * SSZ;
        const uint32_t bbase = abase + A_BYTES;
#pragma unroll
        for (int ss = 0; ss < 4; ss++) {
            const int ksf = ss * 8 * 4;
            uint32_t af[2][4], bf[8][2];
#pragma unroll
            for (int i = 0; i < 2; i++)
                LDM4(af[i][0], af[i][1], af[i][2], af[i][3],
                     abase + a_lane + i * (16 * RSTR * 4) + ksf);
#pragma unroll
            for (int jj = 0; jj < 4; jj++)
                LDM4(bf[2 * jj][0], bf[2 * jj][1], bf[2 * jj + 1][0], bf[2 * jj + 1][1],
                     bbase + b_lane + jj * (16 * RSTR * 4) + ksf);
#pragma unroll
            for (int i = 0; i < 2; i++)
#pragma unroll
                for (int j = 0; j < 8; j++)
                    mma_tf32(acc[i][j], af[i], bf[j]);
        }
        s = (s + 1 == 3) ? 0 : s + 1;
    }

    // Epilogue
#pragma unroll
    for (int i = 0; i < 2; i++) {
        int r0 = row0 + wm * 32 + i * 16 + gid;
#pragma unroll
        for (int j = 0; j < 8; j++) {
            int cc = col0 + wn * 64 + j * 8 + tig * 2;
            if (MODE == 0) {
                *(float2*)(C + (size_t)r0 * DIM + cc)       = make_float2(acc[i][j][0], acc[i][j][1]);
                *(float2*)(C + (size_t)(r0 + 8) * DIM + cc) = make_float2(acc[i][j][2], acc[i][j][3]);
            } else if (MODE == 1) {
                *(float2*)(C + (size_t)r0 * DIM + cc) =
                    make_float2(to_tf32f(acc[i][j][0]), to_tf32f(acc[i][j][1]));
                *(float2*)(C + (size_t)(r0 + 8) * DIM + cc) =
                    make_float2(to_tf32f(acc[i][j][2]), to_tf32f(acc[i][j][3]));
            } else {
                // transposed: g_vt[((b*16+h)*64+d)*SEQ + s], t=row, cc=h*64+d
                int b0 = r0 >> 11, s0 = r0 & 2047;
                int hh = cc >> 6,  dd = cc & 63;
                float* base = C + ((size_t)(b0 * HEADS + hh) * HDIM) * SEQ;
                base[(size_t)(dd)     * SEQ + s0] = to_tf32f(acc[i][j][0]);
                base[(size_t)(dd + 1) * SEQ + s0] = to_tf32f(acc[i][j][1]);
                int r1 = r0 + 8;
                int b1 = r1 >> 11, s1 = r1 & 2047;
                float* base1 = C + ((size_t)(b1 * HEADS + hh) * HDIM) * SEQ;
                base1[(size_t)(dd)     * SEQ + s1] = to_tf32f(acc[i][j][2]);
                base1[(size_t)(dd + 1) * SEQ + s1] = to_tf32f(acc[i][j][3]);
            }
        }
    }
}

__global__ __launch_bounds__(256, 2)
void gemm_qkv() {
    const int mi   = blockIdx.x >> 3;            // 0=Q 1=K 2=V
    const int col0 = (blockIdx.x & 7) * 128;
    const int row0 = blockIdx.y * 128;
    const float* Wt = g_wr + (size_t)mi * DIM * DIM;
    if (mi == 0)      gemm_body<1>(g_qin, Wt, g_q,  row0, col0);
    else if (mi == 1) gemm_body<1>(g_qin, Wt, g_k,  row0, col0);
    else              gemm_body<2>(g_xr,  Wt, g_vt, row0, col0);
}

__global__ __launch_bounds__(256, 2)
void gemm_out(float* __restrict__ out) {
    gemm_body<0>(g_ao, g_wr + (size_t)3 * DIM * DIM, out, blockIdx.y * 128, blockIdx.x * 128);
}

// ===========================================================================
// MMA attention (unchanged from round 8): CTA = (128-q tile, head, batch),
// 8 warps, 64-key passes; S = Q K^T, mask+exp, P via smem, O += P V.
// ===========================================================================
#define AST 68
#define ATTN_SMEM_BYTES ((128*AST + 64*AST + 64*AST + 128*AST) * 4)  // 104448

__global__ __launch_bounds__(256)
void attn_mma() {
    extern __shared__ float afm[];
    float* Ps_f = afm + 128 * AST + 64 * AST + 64 * AST;

    const int tid  = threadIdx.x;
    const int wid  = tid >> 5;
    const int lane = tid & 31;
    const int gid  = lane >> 2;
    const int tig  = lane & 3;
    const int mi   = lane >> 3;
    const int lr   = lane & 7;

    const int qt = blockIdx.x, h = blockIdx.y, b = blockIdx.z;
    const int q0 = qt * 128;

    const uint32_t sb = smem_u32(afm);
    const uint32_t Qb = sb;
    const uint32_t Kb = sb + 128 * AST * 4;
    const uint32_t Vb = Kb + 64 * AST * 4;
    const uint32_t Pb = Vb + 64 * AST * 4;

    const float* Qg = g_q + ((size_t)(b * SEQ + q0)) * DIM + h * HDIM;
#pragma unroll
    for (int it = 0; it < 8; it++) {
        int idx = it * 256 + tid;
        int r = idx >> 4, c4 = idx & 15;
        CPA(Qb + (r * AST + c4 * 4) * 4, Qg + (size_t)r * DIM + c4 * 4);
    }
    CPC();

    const uint32_t a_q = Qb + ((16 * wid + (mi & 1) * 8 + lr) * AST + (mi >> 1) * 4) * 4;
    const uint32_t a_p = Pb + (16 * wid) * AST * 4 + (((mi & 1) * 8 + lr) * AST + (mi >> 1) * 4) * 4;
    const uint32_t boff = ((mi >> 1) * 8 + lr) * AST * 4 + (mi & 1) * 16;

    float o[8][4];
#pragma unroll
    for (int j = 0; j < 8; j++)
#pragma unroll
        for (int r = 0; r < 4; r++) o[j][r] = 0.0f;
    float lp0 = 0.0f, lp1 = 0.0f;
    const int r0g = q0 + 16 * wid + gid;

    for (int p6 = 0; p6 < 6; p6++) {
        const int kt0 = q0 - 128 + p6 * 64;
        if (kt0 < 0 || kt0 >= SEQ) continue;

        __syncthreads();
        const float* Kg = g_k  + ((size_t)(b * SEQ + kt0)) * DIM + h * HDIM;
        const float* Vg = g_vt + ((size_t)((b * HEADS + h) * HDIM)) * SEQ + kt0;
#pragma unroll
        for (int it = 0; it < 4; it++) {
            int idx = it * 256 + tid;
            int r = idx >> 4, c4 = idx & 15;
            CPA(Kb + (r * AST + c4 * 4) * 4, Kg + (size_t)r * DIM + c4 * 4);
            CPA(Vb + (r * AST + c4 * 4) * 4, Vg + (size_t)r * SEQ + c4 * 4);
        }
        CPC(); CPW(0);
        __syncthreads();

        if (kt0 + 63 >= q0 + 16 * wid - 127 && kt0 <= q0 + 16 * wid + 15 + 127) {
            float sc[8][4];
#pragma unroll
            for (int j = 0; j < 8; j++)
#pragma unroll
                for (int r = 0; r < 4; r++) sc[j][r] = 0.0f;
#pragma unroll
            for (int ss = 0; ss < 8; ss++) {
                uint32_t aq[4], bf[8][2];
                LDM4(aq[0], aq[1], aq[2], aq[3], a_q + ss * 32);
#pragma unroll
                for (int jj = 0; jj < 4; jj++)
                    LDM4(bf[2*jj][0], bf[2*jj][1], bf[2*jj+1][0], bf[2*jj+1][1],
                         Kb + jj * (16 * AST * 4) + boff + ss * 32);
#pragma unroll
                for (int j = 0; j < 8; j++) mma_tf32(sc[j], aq, bf[j]);
            }
#pragma unroll
            for (int j = 0; j < 8; j++) {
                int col = kt0 + j * 8 + 2 * tig;
                float e0 = (abs(r0g - col)     < WIN) ? __expf(sc[j][0] * SCALE) : 0.0f;
                float e1 = (abs(r0g - col - 1) < WIN) ? __expf(sc[j][1] * SCALE) : 0.0f;
                float e2 = (abs(r0g + 8 - col)     < WIN) ? __expf(sc[j][2] * SCALE) : 0.0f;
                float e3 = (abs(r0g + 8 - col - 1) < WIN) ? __expf(sc[j][3] * SCALE) : 0.0f;
                e0 = to_tf32f(e0); e1 = to_tf32f(e1);
                e2 = to_tf32f(e2); e3 = to_tf32f(e3);
                lp0 += e0 + e1;
                lp1 += e2 + e3;
                float* p0 = Ps_f + (16 * wid + gid) * AST + j * 8 + 2 * tig;
                float* p1 = Ps_f + (16 * wid + gid + 8) * AST + j * 8 + 2 * tig;
                *(float2*)p0 = make_float2(e0, e1);
                *(float2*)p1 = make_float2(e2, e3);
            }
            __syncwarp();
#pragma unroll
            for (int ss = 0; ss < 8; ss++) {
                uint32_t ap[4], bf[8][2];
                LDM4(ap[0], ap[1], ap[2], ap[3], a_p + ss * 32);
#pragma unroll
                for (int jj = 0; jj < 4; jj++)
                    LDM4(bf[2*jj][0], bf[2*jj][1], bf[2*jj+1][0], bf[2*jj+1][1],
                         Vb + jj * (16 * AST * 4) + boff + ss * 32);
#pragma unroll
                for (int j = 0; j < 8; j++) mma_tf32(o[j], ap, bf[j]);
            }
        }
    }

    lp0 += __shfl_xor_sync(0xffffffff, lp0, 1);
    lp0 += __shfl_xor_sync(0xffffffff, lp0, 2);
    lp1 += __shfl_xor_sync(0xffffffff, lp1, 1);
    lp1 += __shfl_xor_sync(0xffffffff, lp1, 2);
    const float inv0 = 1.0f / lp0;
    const float inv1 = 1.0f / lp1;

    float* Og = g_ao + ((size_t)(b * SEQ + r0g)) * DIM + h * HDIM;
#pragma unroll
    for (int j = 0; j < 8; j++) {
        int c = j * 8 + 2 * tig;
        *(float2*)(Og + c) =
            make_float2(to_tf32f(o[j][0] * inv0), to_tf32f(o[j][1] * inv0));
        *(float2*)(Og + (size_t)8 * DIM + c) =
            make_float2(to_tf32f(o[j][2] * inv1), to_tf32f(o[j][3] * inv1));
    }
}

// ===========================================================================
extern "C" void kernel_launch(void* const* d_in, const int* in_sizes, int n_in,
                              void* d_out, int out_size) {
    const float* x  = (const float*)d_in[0];
    const float* Wq = (const float*)d_in[1];
    const float* Wk = (const float*)d_in[2];
    const float* Wv = (const float*)d_in[3];
    const float* Wo = (const float*)d_in[4];
    float* out = (float*)d_out;

    cudaFuncSetAttribute(gemm_qkv,
                         cudaFuncAttributeMaxDynamicSharedMemorySize, GEMM_SMEM_BYTES);
    cudaFuncSetAttribute(gemm_out,
                         cudaFuncAttributeMaxDynamicSharedMemorySize, GEMM_SMEM_BYTES);
    cudaFuncSetAttribute(attn_mma,
                         cudaFuncAttributeMaxDynamicSharedMemorySize, ATTN_SMEM_BYTES);

    // 0. Prep
    prep_w<<<dim3(32, 32, 4), dim3(32, 8)>>>(Wq, Wk, Wv, Wo);
    prep_x<<<4096, 256>>>(x);

    // 1. RoPE
    rope_kernel<<<(NTOK * 512 + 255) / 256, 256>>>(x);

    // 2. Q,K,V projections (2 CTAs/SM)
    gemm_qkv<<<dim3(24, 32), 256, GEMM_SMEM_BYTES>>>();

    // 3. MMA windowed attention
    attn_mma<<<dim3(SEQ / 128, HEADS, BATCH), 256, ATTN_SMEM_BYTES>>>();

    // 4. Output projection -> d_out
    gemm_out<<<dim3(8, 32), 256, GEMM_SMEM_BYTES>>>(out);
    (void)in_sizes; (void)n_in; (void)out_size;
}

// round 10
// speedup vs baseline: 1.5988x; 1.0035x over previous
#include <cuda_runtime.h>
#include <math.h>
#include <cstdint>

#define BATCH 2
#define SEQ   2048
#define NTOK  (BATCH*SEQ)      // 4096
#define DIM   1024
#define HEADS 16
#define HDIM  64
#define WIN   128
#define SCALE 0.125f           // 1/sqrt(64)

typedef unsigned long long u64;

// Scratch (device globals; no allocation allowed)
__device__ float g_qin[NTOK*DIM];    // rope output, tf32-rounded
__device__ float g_xr [NTOK*DIM];    // x, tf32-rounded
__device__ float g_q  [NTOK*DIM];    // Q, tf32-rounded (gemm epilogue)
__device__ float g_k  [NTOK*DIM];    // K, tf32-rounded
__device__ float g_vt [NTOK*DIM];    // V^T, tf32-rounded: [(b*16+h)*64+d][s]
__device__ float g_ao [NTOK*DIM];    // attention out, tf32-rounded
__device__ float g_wr [4*DIM*DIM];   // W^T, tf32-rounded: [mat][n][k]
__device__ unsigned int g_tctr;      // persistent-GEMM tile counter

__device__ __forceinline__ uint32_t to_tf32(float x) {
    uint32_t u;
    asm("cvt.rna.tf32.f32 %0, %1;" : "=r"(u) : "f"(x));
    return u;
}
__device__ __forceinline__ float to_tf32f(float x) { return __uint_as_float(to_tf32(x)); }

#define CPA(dst, src) \
    asm volatile("cp.async.cg.shared.global [%0], [%1], 16;" :: "r"(dst), "l"(src) : "memory")
#define CPC() asm volatile("cp.async.commit_group;" ::: "memory")
#define CPW(n) asm volatile("cp.async.wait_group %0;" :: "n"(n) : "memory")
#define LDM4(r0, r1, r2, r3, a) \
    asm volatile("ldmatrix.sync.aligned.m8n8.x4.shared.b16 {%0,%1,%2,%3}, [%4];" \
        : "=r"(r0), "=r"(r1), "=r"(r2), "=r"(r3) : "r"(a))

__device__ __forceinline__ uint32_t smem_u32(const void* p) {
    uint32_t a;
    asm("{ .reg .u64 t; cvta.to.shared.u64 t, %1; cvt.u32.u64 %0, t; }" : "=r"(a) : "l"(p));
    return a;
}

__device__ __forceinline__ void mma_tf32(float* c, const uint32_t* a, const uint32_t* b) {
    asm volatile(
        "mma.sync.aligned.m16n8k8.row.col.f32.tf32.tf32.f32 "
        "{%0,%1,%2,%3}, {%4,%5,%6,%7}, {%8,%9}, {%0,%1,%2,%3};"
        : "+f"(c[0]), "+f"(c[1]), "+f"(c[2]), "+f"(c[3])
        : "r"(a[0]), "r"(a[1]), "r"(a[2]), "r"(a[3]), "r"(b[0]), "r"(b[1]));
}

// ===========================================================================
// Prep: transpose + tf32-round all 4 weight matrices ([k][n] -> [n][k])
// ===========================================================================
__global__ void prep_w(const float* __restrict__ w0, const float* __restrict__ w1,
                       const float* __restrict__ w2, const float* __restrict__ w3) {
    __shared__ float t[32][33];
    const int z = blockIdx.z;
    const float* w = (z == 0) ? w0 : (z == 1) ? w1 : (z == 2) ? w2 : w3;
    const int k0 = blockIdx.y * 32, n0 = blockIdx.x * 32;
    for (int r = threadIdx.y; r < 32; r += 8)
        t[r][threadIdx.x] = w[(size_t)(k0 + r) * DIM + n0 + threadIdx.x];
    __syncthreads();
    float* o = g_wr + (size_t)z * DIM * DIM;
    for (int r = threadIdx.y; r < 32; r += 8)
        o[(size_t)(n0 + r) * DIM + k0 + threadIdx.x] = to_tf32f(t[threadIdx.x][r]);
}

// ===========================================================================
// RoPE fused with x-rounding; also resets the persistent tile counter.
// ===========================================================================
__global__ void rope_kernel(const float* __restrict__ x) {
    int idx = blockIdx.x * blockDim.x + threadIdx.x;   // NTOK*512
    if (idx == 0) g_tctr = 0;
    if (idx >= NTOK * 512) return;
    int t   = idx >> 9;
    int rem = idx & 511;
    int h   = rem >> 5;
    int i   = rem & 31;
    int s   = t & (SEQ - 1);

    float inv = expf(-(float)i * (9.210340371976184f / 32.0f));
    float ang = (float)s * inv;
    float sn, cs;
    sincosf(ang, &sn, &cs);

    const float* xp = x     + (size_t)t * DIM + h * HDIM;
    float*       qp = g_qin + (size_t)t * DIM + h * HDIM;
    float*       xr = g_xr  + (size_t)t * DIM + h * HDIM;
    float x1 = xp[i];
    float x2 = xp[i + 32];
    qp[i]      = to_tf32f(x1 * cs - x2 * sn);
    qp[i + 32] = to_tf32f(x2 * cs + x1 * sn);
    xr[i]      = to_tf32f(x1);
    xr[i + 32] = to_tf32f(x2);
}

// ===========================================================================
// TF32 GEMM: CTA 128x128, 256 thr, 8 warps (4x2), warp tile 32x64, BK=32,
// 3-stage cp.async, ldmatrix; 110.6KB smem -> 2 CTAs/SM.
// Epilogue: 0=plain, 1=tf32-rounded, 2=rounded transposed (V).
// ===========================================================================
#define RSTR 36
#define A_BYTES (128 * RSTR * 4)       // 18432
#define B_BYTES (128 * RSTR * 4)       // 18432
#define SSZ     (A_BYTES + B_BYTES)    // 36864
#define GEMM_SMEM_BYTES (3 * SSZ)      // 110592
#define NCHUNK  (DIM / 32)             // 32

extern __shared__ uint32_t dsm[];

template <int MODE>
__device__ __forceinline__ void gemm_body(const float* __restrict__ A,
                                          const float* __restrict__ Wt,
                                          float* __restrict__ C,
                                          int row0, int col0) {
    const int tid  = threadIdx.x;      // 0..255
    const int wid  = tid >> 5;         // 0..7
    const int lane = tid & 31;
    const int gid  = lane >> 2;
    const int tig  = lane & 3;
    const int wm   = wid >> 1;     // 0..3  (x32 rows)
    const int wn   = wid & 1;      // 0..1  (x64 cols)
    const int mi   = lane >> 3;
    const int lr   = lane & 7;

    const uint32_t sb = smem_u32(dsm);

    const uint32_t a_lane = ((wm * 32 + (mi & 1) * 8 + lr) * RSTR + (mi >> 1) * 4) * 4;
    const uint32_t b_lane = ((wn * 64 + (mi >> 1) * 8 + lr) * RSTR + (mi & 1) * 4) * 4;

    float acc[2][8][4];
#pragma unroll
    for (int i = 0; i < 2; i++)
#pragma unroll
        for (int j = 0; j < 8; j++)
#pragma unroll
            for (int r = 0; r < 4; r++) acc[i][j][r] = 0.0f;

#define ISSUE_STAGE(s, c)                                                        \
    {                                                                            \
        uint32_t ab = sb + (s) * SSZ;                                            \
        uint32_t bb = ab + A_BYTES;                                              \
        _Pragma("unroll")                                                        \
        for (int it = 0; it < 4; it++) {                                         \
            int idx = it * 256 + tid;                                            \
            int m = idx >> 3, k4 = idx & 7;                                      \
            CPA(ab + m * 144 + k4 * 16,                                          \
                A + (size_t)(row0 + m) * DIM + (c) * 32 + k4 * 4);               \
            CPA(bb + m * 144 + k4 * 16,                                          \
                Wt + (size_t)(col0 + m) * DIM + (c) * 32 + k4 * 4);              \
        }                                                                        \
        CPC();                                                                   \
    }

    ISSUE_STAGE(0, 0);
    ISSUE_STAGE(1, 1);

    int s = 0;
    for (int c = 0; c < NCHUNK; c++) {
        CPW(1);
        __syncthreads();
        if (c + 2 < NCHUNK) {
            int sn = (s + 2 >= 3) ? s - 1 : s + 2;
            ISSUE_STAGE(sn, c + 2);
        }

        const uint32_t abase = sb + s * SSZ;
        const uint32_t bbase = abase + A_BYTES;
#pragma unroll
        for (int ss = 0; ss < 4; ss++) {
            const int ksf = ss * 8 * 4;
            uint32_t af[2][4], bf[8][2];
#pragma unroll
            for (int i = 0; i < 2; i++)
                LDM4(af[i][0], af[i][1], af[i][2], af[i][3],
                     abase + a_lane + i * (16 * RSTR * 4) + ksf);
#pragma unroll
            for (int jj = 0; jj < 4; jj++)
                LDM4(bf[2 * jj][0], bf[2 * jj][1], bf[2 * jj + 1][0], bf[2 * jj + 1][1],
                     bbase + b_lane + jj * (16 * RSTR * 4) + ksf);
#pragma unroll
            for (int i = 0; i < 2; i++)
#pragma unroll
                for (int j = 0; j < 8; j++)
                    mma_tf32(acc[i][j], af[i], bf[j]);
        }
        s = (s + 1 == 3) ? 0 : s + 1;
    }

    // Epilogue
#pragma unroll
    for (int i = 0; i < 2; i++) {
        int r0 = row0 + wm * 32 + i * 16 + gid;
#pragma unroll
        for (int j = 0; j < 8; j++) {
            int cc = col0 + wn * 64 + j * 8 + tig * 2;
            if (MODE == 0) {
                *(float2*)(C + (size_t)r0 * DIM + cc)       = make_float2(acc[i][j][0], acc[i][j][1]);
                *(float2*)(C + (size_t)(r0 + 8) * DIM + cc) = make_float2(acc[i][j][2], acc[i][j][3]);
            } else if (MODE == 1) {
                *(float2*)(C + (size_t)r0 * DIM + cc) =
                    make_float2(to_tf32f(acc[i][j][0]), to_tf32f(acc[i][j][1]));
                *(float2*)(C + (size_t)(r0 + 8) * DIM + cc) =
                    make_float2(to_tf32f(acc[i][j][2]), to_tf32f(acc[i][j][3]));
            } else {
                int b0 = r0 >> 11, s0 = r0 & 2047;
                int hh = cc >> 6,  dd = cc & 63;
                float* base = C + ((size_t)(b0 * HEADS + hh) * HDIM) * SEQ;
                base[(size_t)(dd)     * SEQ + s0] = to_tf32f(acc[i][j][0]);
                base[(size_t)(dd + 1) * SEQ + s0] = to_tf32f(acc[i][j][1]);
                int r1 = r0 + 8;
                int b1 = r1 >> 11, s1 = r1 & 2047;
                float* base1 = C + ((size_t)(b1 * HEADS + hh) * HDIM) * SEQ;
                base1[(size_t)(dd)     * SEQ + s1] = to_tf32f(acc[i][j][2]);
                base1[(size_t)(dd + 1) * SEQ + s1] = to_tf32f(acc[i][j][3]);
            }
        }
    }
}

// Persistent work-stealing QKV: 296 CTAs pull 128x128 tiles (768 total).
#define QKV_TILES 768

__global__ __launch_bounds__(256, 2)
void gemm_qkv() {
    __shared__ unsigned int s_tile;
    for (;;) {
        __syncthreads();                       // guard smem reuse across tiles
        if (threadIdx.x == 0) s_tile = atomicAdd(&g_tctr, 1u);
        __syncthreads();
        unsigned int tile = s_tile;
        if (tile >= QKV_TILES) return;

        const int mi   = tile >> 8;            // 0=Q 1=K 2=V
        const int rem  = tile & 255;
        const int row0 = (rem >> 3) * 128;
        const int col0 = (rem & 7) * 128;
        const float* Wt = g_wr + (size_t)mi * DIM * DIM;
        if (mi == 0)      gemm_body<1>(g_qin, Wt, g_q,  row0, col0);
        else if (mi == 1) gemm_body<1>(g_qin, Wt, g_k,  row0, col0);
        else              gemm_body<2>(g_xr,  Wt, g_vt, row0, col0);
    }
}

__global__ __launch_bounds__(256, 2)
void gemm_out(float* __restrict__ out) {
    gemm_body<0>(g_ao, g_wr + (size_t)3 * DIM * DIM, out, blockIdx.y * 128, blockIdx.x * 128);
}

// ===========================================================================
// MMA attention (unchanged): CTA = (128-q tile, head, batch), 8 warps,
// 64-key passes; S = Q K^T, mask+exp, P via smem, O += P V.
// ===========================================================================
#define AST 68
#define ATTN_SMEM_BYTES ((128*AST + 64*AST + 64*AST + 128*AST) * 4)  // 104448

__global__ __launch_bounds__(256)
void attn_mma() {
    extern __shared__ float afm[];
    float* Ps_f = afm + 128 * AST + 64 * AST + 64 * AST;

    const int tid  = threadIdx.x;
    const int wid  = tid >> 5;
    const int lane = tid & 31;
    const int gid  = lane >> 2;
    const int tig  = lane & 3;
    const int mi   = lane >> 3;
    const int lr   = lane & 7;

    const int qt = blockIdx.x, h = blockIdx.y, b = blockIdx.z;
    const int q0 = qt * 128;

    const uint32_t sb = smem_u32(afm);
    const uint32_t Qb = sb;
    const uint32_t Kb = sb + 128 * AST * 4;
    const uint32_t Vb = Kb + 64 * AST * 4;
    const uint32_t Pb = Vb + 64 * AST * 4;

    const float* Qg = g_q + ((size_t)(b * SEQ + q0)) * DIM + h * HDIM;
#pragma unroll
    for (int it = 0; it < 8; it++) {
        int idx = it * 256 + tid;
        int r = idx >> 4, c4 = idx & 15;
        CPA(Qb + (r * AST + c4 * 4) * 4, Qg + (size_t)r * DIM + c4 * 4);
    }
    CPC();

    const uint32_t a_q = Qb + ((16 * wid + (mi & 1) * 8 + lr) * AST + (mi >> 1) * 4) * 4;
    const uint32_t a_p = Pb + (16 * wid) * AST * 4 + (((mi & 1) * 8 + lr) * AST + (mi >> 1) * 4) * 4;
    const uint32_t boff = ((mi >> 1) * 8 + lr) * AST * 4 + (mi & 1) * 16;

    float o[8][4];
#pragma unroll
    for (int j = 0; j < 8; j++)
#pragma unroll
        for (int r = 0; r < 4; r++) o[j][r] = 0.0f;
    float lp0 = 0.0f, lp1 = 0.0f;
    const int r0g = q0 + 16 * wid + gid;

    for (int p6 = 0; p6 < 6; p6++) {
        const int kt0 = q0 - 128 + p6 * 64;
        if (kt0 < 0 || kt0 >= SEQ) continue;

        __syncthreads();
        const float* Kg = g_k  + ((size_t)(b * SEQ + kt0)) * DIM + h * HDIM;
        const float* Vg = g_vt + ((size_t)((b * HEADS + h) * HDIM)) * SEQ + kt0;
#pragma unroll
        for (int it = 0; it < 4; it++) {
            int idx = it * 256 + tid;
            int r = idx >> 4, c4 = idx & 15;
            CPA(Kb + (r * AST + c4 * 4) * 4, Kg + (size_t)r * DIM + c4 * 4);
            CPA(Vb + (r * AST + c4 * 4) * 4, Vg + (size_t)r * SEQ + c4 * 4);
        }
        CPC(); CPW(0);
        __syncthreads();

        if (kt0 + 63 >= q0 + 16 * wid - 127 && kt0 <= q0 + 16 * wid + 15 + 127) {
            float sc[8][4];
#pragma unroll
            for (int j = 0; j < 8; j++)
#pragma unroll
                for (int r = 0; r < 4; r++) sc[j][r] = 0.0f;
#pragma unroll
            for (int ss = 0; ss < 8; ss++) {
                uint32_t aq[4], bf[8][2];
                LDM4(aq[0], aq[1], aq[2], aq[3], a_q + ss * 32);
#pragma unroll
                for (int jj = 0; jj < 4; jj++)
                    LDM4(bf[2*jj][0], bf[2*jj][1], bf[2*jj+1][0], bf[2*jj+1][1],
                         Kb + jj * (16 * AST * 4) + boff + ss * 32);
#pragma unroll
                for (int j = 0; j < 8; j++) mma_tf32(sc[j], aq, bf[j]);
            }
#pragma unroll
            for (int j = 0; j < 8; j++) {
                int col = kt0 + j * 8 + 2 * tig;
                float e0 = (abs(r0g - col)     < WIN) ? __expf(sc[j][0] * SCALE) : 0.0f;
                float e1 = (abs(r0g - col - 1) < WIN) ? __expf(sc[j][1] * SCALE) : 0.0f;
                float e2 = (abs(r0g + 8 - col)     < WIN) ? __expf(sc[j][2] * SCALE) : 0.0f;
                float e3 = (abs(r0g + 8 - col - 1) < WIN) ? __expf(sc[j][3] * SCALE) : 0.0f;
                e0 = to_tf32f(e0); e1 = to_tf32f(e1);
                e2 = to_tf32f(e2); e3 = to_tf32f(e3);
                lp0 += e0 + e1;
                lp1 += e2 + e3;
                float* p0 = Ps_f + (16 * wid + gid) * AST + j * 8 + 2 * tig;
                float* p1 = Ps_f + (16 * wid + gid + 8) * AST + j * 8 + 2 * tig;
                *(float2*)p0 = make_float2(e0, e1);
                *(float2*)p1 = make_float2(e2, e3);
            }
            __syncwarp();
#pragma unroll
            for (int ss = 0; ss < 8; ss++) {
                uint32_t ap[4], bf[8][2];
                LDM4(ap[0], ap[1], ap[2], ap[3], a_p + ss * 32);
#pragma unroll
                for (int jj = 0; jj < 4; jj++)
                    LDM4(bf[2*jj][0], bf[2*jj][1], bf[2*jj+1][0], bf[2*jj+1][1],
                         Vb + jj * (16 * AST * 4) + boff + ss * 32);
#pragma unroll
                for (int j = 0; j < 8; j++) mma_tf32(o[j], ap, bf[j]);
            }
        }
    }

    lp0 += __shfl_xor_sync(0xffffffff, lp0, 1);
    lp0 += __shfl_xor_sync(0xffffffff, lp0, 2);
    lp1 += __shfl_xor_sync(0xffffffff, lp1, 1);
    lp1 += __shfl_xor_sync(0xffffffff, lp1, 2);
    const float inv0 = 1.0f / lp0;
    const float inv1 = 1.0f / lp1;

    float* Og = g_ao + ((size_t)(b * SEQ + r0g)) * DIM + h * HDIM;
#pragma unroll
    for (int j = 0; j < 8; j++) {
        int c = j * 8 + 2 * tig;
        *(float2*)(Og + c) =
            make_float2(to_tf32f(o[j][0] * inv0), to_tf32f(o[j][1] * inv0));
        *(float2*)(Og + (size_t)8 * DIM + c) =
            make_float2(to_tf32f(o[j][2] * inv1), to_tf32f(o[j][3] * inv1));
    }
}

// ===========================================================================
extern "C" void kernel_launch(void* const* d_in, const int* in_sizes, int n_in,
                              void* d_out, int out_size) {
    const float* x  = (const float*)d_in[0];
    const float* Wq = (const float*)d_in[1];
    const float* Wk = (const float*)d_in[2];
    const float* Wv = (const float*)d_in[3];
    const float* Wo = (const float*)d_in[4];
    float* out = (float*)d_out;

    cudaFuncSetAttribute(gemm_qkv,
                         cudaFuncAttributeMaxDynamicSharedMemorySize, GEMM_SMEM_BYTES);
    cudaFuncSetAttribute(gemm_out,
                         cudaFuncAttributeMaxDynamicSharedMemorySize, GEMM_SMEM_BYTES);
    cudaFuncSetAttribute(attn_mma,
                         cudaFuncAttributeMaxDynamicSharedMemorySize, ATTN_SMEM_BYTES);

    // 0. Weight prep
    prep_w<<<dim3(32, 32, 4), dim3(32, 8)>>>(Wq, Wk, Wv, Wo);

    // 1. RoPE + x rounding (also resets tile counter)
    rope_kernel<<<(NTOK * 512 + 255) / 256, 256>>>(x);

    // 2. Q,K,V projections — persistent work-stealing, 296 CTAs (2/SM)
    gemm_qkv<<<296, 256, GEMM_SMEM_BYTES>>>();

    // 3. MMA windowed attention
    attn_mma<<<dim3(SEQ / 128, HEADS, BATCH), 256, ATTN_SMEM_BYTES>>>();

    // 4. Output projection -> d_out
    gemm_out<<<dim3(8, 32), 256, GEMM_SMEM_BYTES>>>(out);
    (void)in_sizes; (void)n_in; (void)out_size;
}

// round 11
// speedup vs baseline: 1.8093x; 1.1316x over previous
#include <cuda_runtime.h>
#include <cuda_fp16.h>
#include <math.h>
#include <cstdint>

#define BATCH 2
#define SEQ   2048
#define NTOK  (BATCH*SEQ)      // 4096
#define DIM   1024
#define HEADS 16
#define HDIM  64
#define WIN   128
#define SCALE 0.125f           // 1/sqrt(64)

// Scratch (device globals; no allocation allowed)
__device__ __half g_qin[NTOK*DIM];    // rope output, fp16
__device__ __half g_xr [NTOK*DIM];    // x, fp16
__device__ __half g_q  [NTOK*DIM];    // Q fp16
__device__ __half g_k  [NTOK*DIM];    // K fp16
__device__ __half g_vt [NTOK*DIM];    // V^T fp16: [(b*16+h)*64+d][s]
__device__ __half g_ao [NTOK*DIM];    // attention out fp16
__device__ __half g_wr [4*DIM*DIM];   // W^T fp16: [mat][n][k]
__device__ unsigned int g_tctr;       // persistent-GEMM tile counter

#define CPA(dst, src) \
    asm volatile("cp.async.cg.shared.global [%0], [%1], 16;" :: "r"(dst), "l"(src) : "memory")
#define CPC() asm volatile("cp.async.commit_group;" ::: "memory")
#define CPW(n) asm volatile("cp.async.wait_group %0;" :: "n"(n) : "memory")
#define LDM4(r0, r1, r2, r3, a) \
    asm volatile("ldmatrix.sync.aligned.m8n8.x4.shared.b16 {%0,%1,%2,%3}, [%4];" \
        : "=r"(r0), "=r"(r1), "=r"(r2), "=r"(r3) : "r"(a))

__device__ __forceinline__ uint32_t smem_u32(const void* p) {
    uint32_t a;
    asm("{ .reg .u64 t; cvta.to.shared.u64 t, %1; cvt.u32.u64 %0, t; }" : "=r"(a) : "l"(p));
    return a;
}

__device__ __forceinline__ void mma_f16(float* c, const uint32_t* a, const uint32_t* b) {
    asm volatile(
        "mma.sync.aligned.m16n8k16.row.col.f32.f16.f16.f32 "
        "{%0,%1,%2,%3}, {%4,%5,%6,%7}, {%8,%9}, {%0,%1,%2,%3};"
        : "+f"(c[0]), "+f"(c[1]), "+f"(c[2]), "+f"(c[3])
        : "r"(a[0]), "r"(a[1]), "r"(a[2]), "r"(a[3]), "r"(b[0]), "r"(b[1]));
}

// ===========================================================================
// Prep: transpose + fp16-round all 4 weight matrices ([k][n] -> [n][k])
// ===========================================================================
__global__ void prep_w(const float* __restrict__ w0, const float* __restrict__ w1,
                       const float* __restrict__ w2, const float* __restrict__ w3) {
    __shared__ float t[32][33];
    const int z = blockIdx.z;
    const float* w = (z == 0) ? w0 : (z == 1) ? w1 : (z == 2) ? w2 : w3;
    const int k0 = blockIdx.y * 32, n0 = blockIdx.x * 32;
    for (int r = threadIdx.y; r < 32; r += 8)
        t[r][threadIdx.x] = w[(size_t)(k0 + r) * DIM + n0 + threadIdx.x];
    __syncthreads();
    __half* o = g_wr + (size_t)z * DIM * DIM;
    for (int r = threadIdx.y; r < 32; r += 8)
        o[(size_t)(n0 + r) * DIM + k0 + threadIdx.x] = __float2half_rn(t[threadIdx.x][r]);
}

// ===========================================================================
// RoPE fused with x-rounding; resets the persistent tile counter.
// ===========================================================================
__global__ void rope_kernel(const float* __restrict__ x) {
    int idx = blockIdx.x * blockDim.x + threadIdx.x;   // NTOK*512
    if (idx == 0) g_tctr = 0;
    if (idx >= NTOK * 512) return;
    int t   = idx >> 9;
    int rem = idx & 511;
    int h   = rem >> 5;
    int i   = rem & 31;
    int s   = t & (SEQ - 1);

    float inv = expf(-(float)i * (9.210340371976184f / 32.0f));
    float ang = (float)s * inv;
    float sn, cs;
    sincosf(ang, &sn, &cs);

    const float* xp = x     + (size_t)t * DIM + h * HDIM;
    __half*      qp = g_qin + (size_t)t * DIM + h * HDIM;
    __half*      xr = g_xr  + (size_t)t * DIM + h * HDIM;
    float x1 = xp[i];
    float x2 = xp[i + 32];
    qp[i]      = __float2half_rn(x1 * cs - x2 * sn);
    qp[i + 32] = __float2half_rn(x2 * cs + x1 * sn);
    xr[i]      = __float2half_rn(x1);
    xr[i + 32] = __float2half_rn(x2);
}

// ===========================================================================
// FP16 GEMM: CTA 128x128, 256 thr, 8 warps (4x2), warp tile 32x64, BK=64,
// 3-stage cp.async, ldmatrix.x4 b16; smem rows 64 halves + 8 pad (144B,
// conflict-free). 110.6KB smem -> 2 CTAs/SM.
// Epilogue: 0=fp32 store, 1=fp16 store, 2=fp16 transposed (V).
// ===========================================================================
#define RSTRH 72
#define A_BYTES (128 * RSTRH * 2)      // 18432
#define B_BYTES (128 * RSTRH * 2)      // 18432
#define SSZ     (A_BYTES + B_BYTES)    // 36864
#define GEMM_SMEM_BYTES (3 * SSZ)      // 110592
#define NCHUNK  (DIM / 64)             // 16

extern __shared__ uint32_t dsm[];

template <int MODE, typename OutT>
__device__ __forceinline__ void gemm_body(const __half* __restrict__ A,
                                          const __half* __restrict__ Wt,
                                          OutT* __restrict__ C,
                                          int row0, int col0) {
    const int tid  = threadIdx.x;      // 0..255
    const int wid  = tid >> 5;         // 0..7
    const int lane = tid & 31;
    const int gid  = lane >> 2;
    const int tig  = lane & 3;
    const int wm   = wid >> 1;     // 0..3  (x32 rows)
    const int wn   = wid & 1;      // 0..1  (x64 cols)
    const int mi   = lane >> 3;
    const int lr   = lane & 7;

    const uint32_t sb = smem_u32(dsm);

    const uint32_t a_lane = ((wm * 32 + (mi & 1) * 8 + lr) * RSTRH + (mi >> 1) * 8) * 2;
    const uint32_t b_lane = ((wn * 64 + (mi >> 1) * 8 + lr) * RSTRH + (mi & 1) * 8) * 2;

    float acc[2][8][4];
#pragma unroll
    for (int i = 0; i < 2; i++)
#pragma unroll
        for (int j = 0; j < 8; j++)
#pragma unroll
            for (int r = 0; r < 4; r++) acc[i][j][r] = 0.0f;

    // A, B tiles: 128 rows x 8 chunks of 8 halves (16B): 1024 slots, 4/thread each
#define ISSUE_STAGE(s, c)                                                        \
    {                                                                            \
        uint32_t ab = sb + (s) * SSZ;                                            \
        uint32_t bb = ab + A_BYTES;                                              \
        _Pragma("unroll")                                                        \
        for (int it = 0; it < 4; it++) {                                         \
            int idx = it * 256 + tid;                                            \
            int m = idx >> 3, k8 = idx & 7;                                      \
            CPA(ab + m * 144 + k8 * 16,                                          \
                A + (size_t)(row0 + m) * DIM + (c) * 64 + k8 * 8);               \
            CPA(bb + m * 144 + k8 * 16,                                          \
                Wt + (size_t)(col0 + m) * DIM + (c) * 64 + k8 * 8);              \
        }                                                                        \
        CPC();                                                                   \
    }

    ISSUE_STAGE(0, 0);
    ISSUE_STAGE(1, 1);

    int s = 0;
    for (int c = 0; c < NCHUNK; c++) {
        CPW(1);
        __syncthreads();
        if (c + 2 < NCHUNK) {
            int sn = (s + 2 >= 3) ? s - 1 : s + 2;
            ISSUE_STAGE(sn, c + 2);
        }

        const uint32_t abase = sb + s * SSZ;
        const uint32_t bbase = abase + A_BYTES;
#pragma unroll
        for (int ss = 0; ss < 4; ss++) {     // k substeps of 16 halves = 32 B
            const int ksf = ss * 32;
            uint32_t af[2][4], bf[8][2];
#pragma unroll
            for (int i = 0; i < 2; i++)
                LDM4(af[i][0], af[i][1], af[i][2], af[i][3],
                     abase + a_lane + i * (16 * RSTRH * 2) + ksf);
#pragma unroll
            for (int jj = 0; jj < 4; jj++)
                LDM4(bf[2 * jj][0], bf[2 * jj][1], bf[2 * jj + 1][0], bf[2 * jj + 1][1],
                     bbase + b_lane + jj * (16 * RSTRH * 2) + ksf);
#pragma unroll
            for (int i = 0; i < 2; i++)
#pragma unroll
                for (int j = 0; j < 8; j++)
                    mma_f16(acc[i][j], af[i], bf[j]);
        }
        s = (s + 1 == 3) ? 0 : s + 1;
    }

    // Epilogue
#pragma unroll
    for (int i = 0; i < 2; i++) {
        int r0 = row0 + wm * 32 + i * 16 + gid;
#pragma unroll
        for (int j = 0; j < 8; j++) {
            int cc = col0 + wn * 64 + j * 8 + tig * 2;
            if (MODE == 0) {
                float* Cf = (float*)C;
                *(float2*)(Cf + (size_t)r0 * DIM + cc)       = make_float2(acc[i][j][0], acc[i][j][1]);
                *(float2*)(Cf + (size_t)(r0 + 8) * DIM + cc) = make_float2(acc[i][j][2], acc[i][j][3]);
            } else if (MODE == 1) {
                __half* Ch = (__half*)C;
                *(__half2*)(Ch + (size_t)r0 * DIM + cc) =
                    __floats2half2_rn(acc[i][j][0], acc[i][j][1]);
                *(__half2*)(Ch + (size_t)(r0 + 8) * DIM + cc) =
                    __floats2half2_rn(acc[i][j][2], acc[i][j][3]);
            } else {
                __half* Ch = (__half*)C;
                int b0 = r0 >> 11, s0 = r0 & 2047;
                int hh = cc >> 6,  dd = cc & 63;
                __half* base = Ch + ((size_t)(b0 * HEADS + hh) * HDIM) * SEQ;
                base[(size_t)(dd)     * SEQ + s0] = __float2half_rn(acc[i][j][0]);
                base[(size_t)(dd + 1) * SEQ + s0] = __float2half_rn(acc[i][j][1]);
                int r1 = r0 + 8;
                int b1 = r1 >> 11, s1 = r1 & 2047;
                __half* base1 = Ch + ((size_t)(b1 * HEADS + hh) * HDIM) * SEQ;
                base1[(size_t)(dd)     * SEQ + s1] = __float2half_rn(acc[i][j][2]);
                base1[(size_t)(dd + 1) * SEQ + s1] = __float2half_rn(acc[i][j][3]);
            }
        }
    }
}

// Persistent work-stealing QKV: 296 CTAs pull 128x128 tiles (768 total).
#define QKV_TILES 768

__global__ __launch_bounds__(256, 2)
void gemm_qkv() {
    __shared__ unsigned int s_tile;
    for (;;) {
        __syncthreads();
        if (threadIdx.x == 0) s_tile = atomicAdd(&g_tctr, 1u);
        __syncthreads();
        unsigned int tile = s_tile;
        if (tile >= QKV_TILES) return;

        const int mi   = tile >> 8;            // 0=Q 1=K 2=V
        const int rem  = tile & 255;
        const int row0 = (rem >> 3) * 128;
        const int col0 = (rem & 7) * 128;
        const __half* Wt = g_wr + (size_t)mi * DIM * DIM;
        if (mi == 0)      gemm_body<1>(g_qin, Wt, g_q,  row0, col0);
        else if (mi == 1) gemm_body<1>(g_qin, Wt, g_k,  row0, col0);
        else              gemm_body<2>(g_xr,  Wt, g_vt, row0, col0);
    }
}

__global__ __launch_bounds__(256, 2)
void gemm_out(float* __restrict__ out) {
    gemm_body<0>(g_ao, g_wr + (size_t)3 * DIM * DIM, out, blockIdx.y * 128, blockIdx.x * 128);
}

// ===========================================================================
// FP16 MMA attention: CTA = (128-q tile, head, batch), 8 warps, 64-key
// passes; S = Q K^T, mask+exp, P (fp16) via smem, O += P V (V^T fp16).
// smem halves, stride 72 (144B rows): Qs[128] | Ks[64] | Vt[64] | Ps[128]
// ===========================================================================
#define ATTN_SMEM_BYTES ((128*RSTRH + 64*RSTRH + 64*RSTRH + 128*RSTRH) * 2)  // 55296

__global__ __launch_bounds__(256)
void attn_mma() {
    extern __shared__ __half afh[];
    __half* Ps_h = afh + 128 * RSTRH + 64 * RSTRH + 64 * RSTRH;

    const int tid  = threadIdx.x;
    const int wid  = tid >> 5;
    const int lane = tid & 31;
    const int gid  = lane >> 2;
    const int tig  = lane & 3;
    const int mi   = lane >> 3;
    const int lr   = lane & 7;

    const int qt = blockIdx.x, h = blockIdx.y, b = blockIdx.z;
    const int q0 = qt * 128;

    const uint32_t sb = smem_u32(afh);
    const uint32_t Qb = sb;
    const uint32_t Kb = sb + 128 * RSTRH * 2;
    const uint32_t Vb = Kb + 64 * RSTRH * 2;
    const uint32_t Pb = Vb + 64 * RSTRH * 2;

    // Q tile (128 x 64 halves): 1024 16B slots, 4/thread
    const __half* Qg = g_q + ((size_t)(b * SEQ + q0)) * DIM + h * HDIM;
#pragma unroll
    for (int it = 0; it < 4; it++) {
        int idx = it * 256 + tid;
        int r = idx >> 3, c8 = idx & 7;
        CPA(Qb + r * 144 + c8 * 16, Qg + (size_t)r * DIM + c8 * 8);
    }
    CPC();

    const uint32_t a_q = Qb + ((16 * wid + (mi & 1) * 8 + lr) * RSTRH + (mi >> 1) * 8) * 2;
    const uint32_t a_p = Pb + ((16 * wid + (mi & 1) * 8 + lr) * RSTRH + (mi >> 1) * 8) * 2;
    const uint32_t boff = ((mi >> 1) * 8 + lr) * 144 + (mi & 1) * 16;

    float o[8][4];
#pragma unroll
    for (int j = 0; j < 8; j++)
#pragma unroll
        for (int r = 0; r < 4; r++) o[j][r] = 0.0f;
    float lp0 = 0.0f, lp1 = 0.0f;
    const int r0g = q0 + 16 * wid + gid;

    for (int p6 = 0; p6 < 6; p6++) {
        const int kt0 = q0 - 128 + p6 * 64;
        if (kt0 < 0 || kt0 >= SEQ) continue;

        __syncthreads();
        const __half* Kg = g_k  + ((size_t)(b * SEQ + kt0)) * DIM + h * HDIM;
        const __half* Vg = g_vt + ((size_t)((b * HEADS + h) * HDIM)) * SEQ + kt0;
        // K, V: each 64 rows x 8 chunks = 512 slots, 2/thread
#pragma unroll
        for (int it = 0; it < 2; it++) {
            int idx = it * 256 + tid;
            int r = idx >> 3, c8 = idx & 7;
            CPA(Kb + r * 144 + c8 * 16, Kg + (size_t)r * DIM + c8 * 8);
            CPA(Vb + r * 144 + c8 * 16, Vg + (size_t)r * SEQ + c8 * 8);
        }
        CPC(); CPW(0);
        __syncthreads();

        if (kt0 + 63 >= q0 + 16 * wid - 127 && kt0 <= q0 + 16 * wid + 15 + 127) {
            // ---- S = Q K^T ----
            float sc[8][4];
#pragma unroll
            for (int j = 0; j < 8; j++)
#pragma unroll
                for (int r = 0; r < 4; r++) sc[j][r] = 0.0f;
#pragma unroll
            for (int ss = 0; ss < 4; ss++) {
                uint32_t aq[4], bf[8][2];
                LDM4(aq[0], aq[1], aq[2], aq[3], a_q + ss * 32);
#pragma unroll
                for (int jj = 0; jj < 4; jj++)
                    LDM4(bf[2*jj][0], bf[2*jj][1], bf[2*jj+1][0], bf[2*jj+1][1],
                         Kb + jj * (16 * RSTRH * 2) + boff + ss * 32);
#pragma unroll
                for (int j = 0; j < 8; j++) mma_f16(sc[j], aq, bf[j]);
            }
            // ---- mask + exp + P store (fp16) ----
#pragma unroll
            for (int j = 0; j < 8; j++) {
                int col = kt0 + j * 8 + 2 * tig;
                float e0 = (abs(r0g - col)     < WIN) ? __expf(sc[j][0] * SCALE) : 0.0f;
                float e1 = (abs(r0g - col - 1) < WIN) ? __expf(sc[j][1] * SCALE) : 0.0f;
                float e2 = (abs(r0g + 8 - col)     < WIN) ? __expf(sc[j][2] * SCALE) : 0.0f;
                float e3 = (abs(r0g + 8 - col - 1) < WIN) ? __expf(sc[j][3] * SCALE) : 0.0f;
                __half2 h01 = __floats2half2_rn(e0, e1);
                __half2 h23 = __floats2half2_rn(e2, e3);
                float2 f01 = __half22float2(h01);
                float2 f23 = __half22float2(h23);
                lp0 += f01.x + f01.y;
                lp1 += f23.x + f23.y;
                *(__half2*)&Ps_h[(16 * wid + gid) * RSTRH + j * 8 + 2 * tig]     = h01;
                *(__half2*)&Ps_h[(16 * wid + gid + 8) * RSTRH + j * 8 + 2 * tig] = h23;
            }
            __syncwarp();
            // ---- O += P V ----
#pragma unroll
            for (int ss = 0; ss < 4; ss++) {
                uint32_t ap[4], bf[8][2];
                LDM4(ap[0], ap[1], ap[2], ap[3], a_p + ss * 32);
#pragma unroll
                for (int jj = 0; jj < 4; jj++)
                    LDM4(bf[2*jj][0], bf[2*jj][1], bf[2*jj+1][0], bf[2*jj+1][1],
                         Vb + jj * (16 * RSTRH * 2) + boff + ss * 32);
#pragma unroll
                for (int j = 0; j < 8; j++) mma_f16(o[j], ap, bf[j]);
            }
        }
    }

    lp0 += __shfl_xor_sync(0xffffffff, lp0, 1);
    lp0 += __shfl_xor_sync(0xffffffff, lp0, 2);
    lp1 += __shfl_xor_sync(0xffffffff, lp1, 1);
    lp1 += __shfl_xor_sync(0xffffffff, lp1, 2);
    const float inv0 = 1.0f / lp0;
    const float inv1 = 1.0f / lp1;

    __half* Og = g_ao + ((size_t)(b * SEQ + r0g)) * DIM + h * HDIM;
#pragma unroll
    for (int j = 0; j < 8; j++) {
        int c = j * 8 + 2 * tig;
        *(__half2*)(Og + c) = __floats2half2_rn(o[j][0] * inv0, o[j][1] * inv0);
        *(__half2*)(Og + (size_t)8 * DIM + c) = __floats2half2_rn(o[j][2] * inv1, o[j][3] * inv1);
    }
}

// ===========================================================================
extern "C" void kernel_launch(void* const* d_in, const int* in_sizes, int n_in,
                              void* d_out, int out_size) {
    const float* x  = (const float*)d_in[0];
    const float* Wq = (const float*)d_in[1];
    const float* Wk = (const float*)d_in[2];
    const float* Wv = (const float*)d_in[3];
    const float* Wo = (const float*)d_in[4];
    float* out = (float*)d_out;

    cudaFuncSetAttribute(gemm_qkv,
                         cudaFuncAttributeMaxDynamicSharedMemorySize, GEMM_SMEM_BYTES);
    cudaFuncSetAttribute(gemm_out,
                         cudaFuncAttributeMaxDynamicSharedMemorySize, GEMM_SMEM_BYTES);
    cudaFuncSetAttribute(attn_mma,
                         cudaFuncAttributeMaxDynamicSharedMemorySize, ATTN_SMEM_BYTES);

    // 0. Weight prep
    prep_w<<<dim3(32, 32, 4), dim3(32, 8)>>>(Wq, Wk, Wv, Wo);

    // 1. RoPE + x rounding (resets tile counter)
    rope_kernel<<<(NTOK * 512 + 255) / 256, 256>>>(x);

    // 2. Q,K,V projections — persistent, 296 CTAs (2/SM)
    gemm_qkv<<<296, 256, GEMM_SMEM_BYTES>>>();

    // 3. FP16 MMA windowed attention
    attn_mma<<<dim3(SEQ / 128, HEADS, BATCH), 256, ATTN_SMEM_BYTES>>>();

    // 4. Output projection -> d_out (fp32)
    gemm_out<<<dim3(8, 32), 256, GEMM_SMEM_BYTES>>>(out);
    (void)in_sizes; (void)n_in; (void)out_size;
}

// round 12
// speedup vs baseline: 2.7282x; 1.5079x over previous
#include <cuda_runtime.h>
#include <cuda_fp16.h>
#include <math.h>
#include <cstdint>

#define BATCH 2
#define SEQ   2048
#define NTOK  (BATCH*SEQ)      // 4096
#define DIM   1024
#define HEADS 16
#define HDIM  64
#define WIN   128
#define SCALE 0.125f           // 1/sqrt(64)

// Scratch (device globals; no allocation allowed)
__device__ __half g_qin[NTOK*DIM];    // rope output, fp16
__device__ __half g_xr [NTOK*DIM];    // x, fp16
__device__ __half g_q  [NTOK*DIM];    // Q fp16
__device__ __half g_k  [NTOK*DIM];    // K fp16
__device__ __half g_vt [NTOK*DIM];    // V^T fp16: [(b*16+h)*64+d][s]
__device__ __half g_ao [NTOK*DIM];    // attention out fp16
__device__ __half g_wr [4*DIM*DIM];   // W^T fp16: [mat][n][k]
__device__ unsigned int g_tctr;       // persistent-GEMM tile counter

#define CPA(dst, src) \
    asm volatile("cp.async.cg.shared.global [%0], [%1], 16;" :: "r"(dst), "l"(src) : "memory")
#define CPC() asm volatile("cp.async.commit_group;" ::: "memory")
#define CPW(n) asm volatile("cp.async.wait_group %0;" :: "n"(n) : "memory")
#define LDM4(r0, r1, r2, r3, a) \
    asm volatile("ldmatrix.sync.aligned.m8n8.x4.shared.b16 {%0,%1,%2,%3}, [%4];" \
        : "=r"(r0), "=r"(r1), "=r"(r2), "=r"(r3) : "r"(a))

__device__ __forceinline__ uint32_t smem_u32(const void* p) {
    uint32_t a;
    asm("{ .reg .u64 t; cvta.to.shared.u64 t, %1; cvt.u32.u64 %0, t; }" : "=r"(a) : "l"(p));
    return a;
}

__device__ __forceinline__ void mma_f16(float* c, const uint32_t* a, const uint32_t* b) {
    asm volatile(
        "mma.sync.aligned.m16n8k16.row.col.f32.f16.f16.f32 "
        "{%0,%1,%2,%3}, {%4,%5,%6,%7}, {%8,%9}, {%0,%1,%2,%3};"
        : "+f"(c[0]), "+f"(c[1]), "+f"(c[2]), "+f"(c[3])
        : "r"(a[0]), "r"(a[1]), "r"(a[2]), "r"(a[3]), "r"(b[0]), "r"(b[1]));
}

// ===========================================================================
// Prep: transpose + fp16-round all 4 weight matrices ([k][n] -> [n][k])
// ===========================================================================
__global__ void prep_w(const float* __restrict__ w0, const float* __restrict__ w1,
                       const float* __restrict__ w2, const float* __restrict__ w3) {
    __shared__ float t[32][33];
    const int z = blockIdx.z;
    const float* w = (z == 0) ? w0 : (z == 1) ? w1 : (z == 2) ? w2 : w3;
    const int k0 = blockIdx.y * 32, n0 = blockIdx.x * 32;
    for (int r = threadIdx.y; r < 32; r += 8)
        t[r][threadIdx.x] = w[(size_t)(k0 + r) * DIM + n0 + threadIdx.x];
    __syncthreads();
    __half* o = g_wr + (size_t)z * DIM * DIM;
    for (int r = threadIdx.y; r < 32; r += 8)
        o[(size_t)(n0 + r) * DIM + k0 + threadIdx.x] = __float2half_rn(t[threadIdx.x][r]);
}

// ===========================================================================
// RoPE fused with x-rounding; resets the persistent tile counter.
// ===========================================================================
__global__ void rope_kernel(const float* __restrict__ x) {
    int idx = blockIdx.x * blockDim.x + threadIdx.x;   // NTOK*512
    if (idx == 0) g_tctr = 0;
    if (idx >= NTOK * 512) return;
    int t   = idx >> 9;
    int rem = idx & 511;
    int h   = rem >> 5;
    int i   = rem & 31;
    int s   = t & (SEQ - 1);

    float inv = expf(-(float)i * (9.210340371976184f / 32.0f));
    float ang = (float)s * inv;
    float sn, cs;
    sincosf(ang, &sn, &cs);

    const float* xp = x     + (size_t)t * DIM + h * HDIM;
    __half*      qp = g_qin + (size_t)t * DIM + h * HDIM;
    __half*      xr = g_xr  + (size_t)t * DIM + h * HDIM;
    float x1 = xp[i];
    float x2 = xp[i + 32];
    qp[i]      = __float2half_rn(x1 * cs - x2 * sn);
    qp[i + 32] = __float2half_rn(x2 * cs + x1 * sn);
    xr[i]      = __float2half_rn(x1);
    xr[i + 32] = __float2half_rn(x2);
}

// ===========================================================================
// FP16 GEMM (unchanged from round 11): CTA 128x128, 256 thr, warp tile 32x64,
// BK=64, 3-stage cp.async, ldmatrix; 110.6KB smem -> 2 CTAs/SM.
// ===========================================================================
#define RSTRH 72
#define A_BYTES (128 * RSTRH * 2)      // 18432
#define B_BYTES (128 * RSTRH * 2)      // 18432
#define SSZ     (A_BYTES + B_BYTES)    // 36864
#define GEMM_SMEM_BYTES (3 * SSZ)      // 110592
#define NCHUNK  (DIM / 64)             // 16

extern __shared__ uint32_t dsm[];

template <int MODE, typename OutT>
__device__ __forceinline__ void gemm_body(const __half* __restrict__ A,
                                          const __half* __restrict__ Wt,
                                          OutT* __restrict__ C,
                                          int row0, int col0) {
    const int tid  = threadIdx.x;
    const int wid  = tid >> 5;
    const int lane = tid & 31;
    const int gid  = lane >> 2;
    const int tig  = lane & 3;
    const int wm   = wid >> 1;
    const int wn   = wid & 1;
    const int mi   = lane >> 3;
    const int lr   = lane & 7;

    const uint32_t sb = smem_u32(dsm);

    const uint32_t a_lane = ((wm * 32 + (mi & 1) * 8 + lr) * RSTRH + (mi >> 1) * 8) * 2;
    const uint32_t b_lane = ((wn * 64 + (mi >> 1) * 8 + lr) * RSTRH + (mi & 1) * 8) * 2;

    float acc[2][8][4];
#pragma unroll
    for (int i = 0; i < 2; i++)
#pragma unroll
        for (int j = 0; j < 8; j++)
#pragma unroll
            for (int r = 0; r < 4; r++) acc[i][j][r] = 0.0f;

#define ISSUE_STAGE(s, c)                                                        \
    {                                                                            \
        uint32_t ab = sb + (s) * SSZ;                                            \
        uint32_t bb = ab + A_BYTES;                                              \
        _Pragma("unroll")                                                        \
        for (int it = 0; it < 4; it++) {                                         \
            int idx = it * 256 + tid;                                            \
            int m = idx >> 3, k8 = idx & 7;                                      \
            CPA(ab + m * 144 + k8 * 16,                                          \
                A + (size_t)(row0 + m) * DIM + (c) * 64 + k8 * 8);               \
            CPA(bb + m * 144 + k8 * 16,                                          \
                Wt + (size_t)(col0 + m) * DIM + (c) * 64 + k8 * 8);              \
        }                                                                        \
        CPC();                                                                   \
    }

    ISSUE_STAGE(0, 0);
    ISSUE_STAGE(1, 1);

    int s = 0;
    for (int c = 0; c < NCHUNK; c++) {
        CPW(1);
        __syncthreads();
        if (c + 2 < NCHUNK) {
            int sn = (s + 2 >= 3) ? s - 1 : s + 2;
            ISSUE_STAGE(sn, c + 2);
        }

        const uint32_t abase = sb + s * SSZ;
        const uint32_t bbase = abase + A_BYTES;
#pragma unroll
        for (int ss = 0; ss < 4; ss++) {
            const int ksf = ss * 32;
            uint32_t af[2][4], bf[8][2];
#pragma unroll
            for (int i = 0; i < 2; i++)
                LDM4(af[i][0], af[i][1], af[i][2], af[i][3],
                     abase + a_lane + i * (16 * RSTRH * 2) + ksf);
#pragma unroll
            for (int jj = 0; jj < 4; jj++)
                LDM4(bf[2 * jj][0], bf[2 * jj][1], bf[2 * jj + 1][0], bf[2 * jj + 1][1],
                     bbase + b_lane + jj * (16 * RSTRH * 2) + ksf);
#pragma unroll
            for (int i = 0; i < 2; i++)
#pragma unroll
                for (int j = 0; j < 8; j++)
                    mma_f16(acc[i][j], af[i], bf[j]);
        }
        s = (s + 1 == 3) ? 0 : s + 1;
    }

#pragma unroll
    for (int i = 0; i < 2; i++) {
        int r0 = row0 + wm * 32 + i * 16 + gid;
#pragma unroll
        for (int j = 0; j < 8; j++) {
            int cc = col0 + wn * 64 + j * 8 + tig * 2;
            if (MODE == 0) {
                float* Cf = (float*)C;
                *(float2*)(Cf + (size_t)r0 * DIM + cc)       = make_float2(acc[i][j][0], acc[i][j][1]);
                *(float2*)(Cf + (size_t)(r0 + 8) * DIM + cc) = make_float2(acc[i][j][2], acc[i][j][3]);
            } else if (MODE == 1) {
                __half* Ch = (__half*)C;
                *(__half2*)(Ch + (size_t)r0 * DIM + cc) =
                    __floats2half2_rn(acc[i][j][0], acc[i][j][1]);
                *(__half2*)(Ch + (size_t)(r0 + 8) * DIM + cc) =
                    __floats2half2_rn(acc[i][j][2], acc[i][j][3]);
            } else {
                __half* Ch = (__half*)C;
                int b0 = r0 >> 11, s0 = r0 & 2047;
                int hh = cc >> 6,  dd = cc & 63;
                __half* base = Ch + ((size_t)(b0 * HEADS + hh) * HDIM) * SEQ;
                base[(size_t)(dd)     * SEQ + s0] = __float2half_rn(acc[i][j][0]);
                base[(size_t)(dd + 1) * SEQ + s0] = __float2half_rn(acc[i][j][1]);
                int r1 = r0 + 8;
                int b1 = r1 >> 11, s1 = r1 & 2047;
                __half* base1 = Ch + ((size_t)(b1 * HEADS + hh) * HDIM) * SEQ;
                base1[(size_t)(dd)     * SEQ + s1] = __float2half_rn(acc[i][j][2]);
                base1[(size_t)(dd + 1) * SEQ + s1] = __float2half_rn(acc[i][j][3]);
            }
        }
    }
}

#define QKV_TILES 768

__global__ __launch_bounds__(256, 2)
void gemm_qkv() {
    __shared__ unsigned int s_tile;
    for (;;) {
        __syncthreads();
        if (threadIdx.x == 0) s_tile = atomicAdd(&g_tctr, 1u);
        __syncthreads();
        unsigned int tile = s_tile;
        if (tile >= QKV_TILES) return;

        const int mi   = tile >> 8;
        const int rem  = tile & 255;
        const int row0 = (rem >> 3) * 128;
        const int col0 = (rem & 7) * 128;
        const __half* Wt = g_wr + (size_t)mi * DIM * DIM;
        if (mi == 0)      gemm_body<1>(g_qin, Wt, g_q,  row0, col0);
        else if (mi == 1) gemm_body<1>(g_qin, Wt, g_k,  row0, col0);
        else              gemm_body<2>(g_xr,  Wt, g_vt, row0, col0);
    }
}

__global__ __launch_bounds__(256, 2)
void gemm_out(float* __restrict__ out) {
    gemm_body<0>(g_ao, g_wr + (size_t)3 * DIM * DIM, out, blockIdx.y * 128, blockIdx.x * 128);
}

// ===========================================================================
// FP16 MMA attention v2: double-buffered K/V (cp.async groups), pass-range
// trimming, warp-uniform mask specialization (full passes skip masks; fully
// masked 8-col blocks skip exp).
// smem halves: Q[128*72] | K0[64*72] | V0[64*72] | K1[64*72] | V1[64*72] | P[128*72]
// ===========================================================================
#define KVSZ (64 * RSTRH * 2)          // 9216 B
#define ATTN_SMEM_BYTES (128*RSTRH*2 + 4*KVSZ + 128*RSTRH*2)  // 73728

__global__ __launch_bounds__(256)
void attn_mma() {
    extern __shared__ __half afh[];

    const int tid  = threadIdx.x;
    const int wid  = tid >> 5;
    const int lane = tid & 31;
    const int gid  = lane >> 2;
    const int tig  = lane & 3;
    const int mi   = lane >> 3;
    const int lr   = lane & 7;

    const int qt = blockIdx.x, h = blockIdx.y, b = blockIdx.z;
    const int q0 = qt * 128;

    const uint32_t sb = smem_u32(afh);
    const uint32_t Qb = sb;
    const uint32_t KV0 = sb + 128 * RSTRH * 2;
    const uint32_t Pb  = KV0 + 4 * KVSZ;
    __half* Ps_h = afh + 128 * RSTRH + 4 * 64 * RSTRH;

    // Q tile (128 x 64 halves): 1024 16B slots, 4/thread
    const __half* Qg = g_q + ((size_t)(b * SEQ + q0)) * DIM + h * HDIM;
#pragma unroll
    for (int it = 0; it < 4; it++) {
        int idx = it * 256 + tid;
        int r = idx >> 3, c8 = idx & 7;
        CPA(Qb + r * 144 + c8 * 16, Qg + (size_t)r * DIM + c8 * 8);
    }
    CPC();

    const __half* Kgb = g_k  + ((size_t)(b * SEQ)) * DIM + h * HDIM;
    const __half* Vgb = g_vt + ((size_t)((b * HEADS + h) * HDIM)) * SEQ;

#define ISSUE_KV(kt0, nb)                                                        \
    {                                                                            \
        uint32_t kb = KV0 + (nb) * 2 * KVSZ;                                     \
        uint32_t vb = kb + KVSZ;                                                 \
        const __half* Kg = Kgb + (size_t)(kt0) * DIM;                            \
        const __half* Vg = Vgb + (kt0);                                          \
        _Pragma("unroll")                                                        \
        for (int it = 0; it < 2; it++) {                                         \
            int idx = it * 256 + tid;                                            \
            int r = idx >> 3, c8 = idx & 7;                                      \
            CPA(kb + r * 144 + c8 * 16, Kg + (size_t)r * DIM + c8 * 8);          \
            CPA(vb + r * 144 + c8 * 16, Vg + (size_t)r * SEQ + c8 * 8);          \
        }                                                                        \
        CPC();                                                                   \
    }

    const uint32_t a_q = Qb + ((16 * wid + (mi & 1) * 8 + lr) * RSTRH + (mi >> 1) * 8) * 2;
    const uint32_t a_p = Pb + ((16 * wid + (mi & 1) * 8 + lr) * RSTRH + (mi >> 1) * 8) * 2;
    const uint32_t boff = ((mi >> 1) * 8 + lr) * 144 + (mi & 1) * 16;

    float o[8][4];
#pragma unroll
    for (int j = 0; j < 8; j++)
#pragma unroll
        for (int r = 0; r < 4; r++) o[j][r] = 0.0f;
    float lp0 = 0.0f, lp1 = 0.0f;
    const int r0g = q0 + 16 * wid + gid;

    const int p_lo = (q0 == 0) ? 2 : 0;
    const int p_hi = min(5, (SEQ + 64 - q0) / 64);

    ISSUE_KV(q0 - 128 + p_lo * 64, 0);

    int nb = 0;
    for (int p = p_lo; p <= p_hi; p++) {
        const int kt0 = q0 - 128 + p * 64;

        __syncthreads();                       // alt buffer free (pass p-1 done)
        if (p < p_hi) { ISSUE_KV(kt0 + 64, nb ^ 1); CPW(1); }
        else CPW(0);
        __syncthreads();

        const int d = q0 + 16 * wid - kt0;     // warp-uniform
        if (d > -143 && d < 191) {
            const uint32_t kbuf = KV0 + nb * 2 * KVSZ;
            const uint32_t vbuf = kbuf + KVSZ;

            // ---- S = Q K^T ----
            float sc[8][4];
#pragma unroll
            for (int j = 0; j < 8; j++)
#pragma unroll
                for (int r = 0; r < 4; r++) sc[j][r] = 0.0f;
#pragma unroll
            for (int ss = 0; ss < 4; ss++) {
                uint32_t aq[4], bf[8][2];
                LDM4(aq[0], aq[1], aq[2], aq[3], a_q + ss * 32);
#pragma unroll
                for (int jj = 0; jj < 4; jj++)
                    LDM4(bf[2*jj][0], bf[2*jj][1], bf[2*jj+1][0], bf[2*jj+1][1],
                         kbuf + jj * (16 * RSTRH * 2) + boff + ss * 32);
#pragma unroll
                for (int j = 0; j < 8; j++) mma_f16(sc[j], aq, bf[j]);
            }

            // ---- mask + exp + P store ----
            const bool full = (d >= -64) && (d <= 112);
            if (full) {
#pragma unroll
                for (int j = 0; j < 8; j++) {
                    float e0 = __expf(sc[j][0] * SCALE);
                    float e1 = __expf(sc[j][1] * SCALE);
                    float e2 = __expf(sc[j][2] * SCALE);
                    float e3 = __expf(sc[j][3] * SCALE);
                    __half2 h01 = __floats2half2_rn(e0, e1);
                    __half2 h23 = __floats2half2_rn(e2, e3);
                    float2 f01 = __half22float2(h01);
                    float2 f23 = __half22float2(h23);
                    lp0 += f01.x + f01.y;
                    lp1 += f23.x + f23.y;
                    *(__half2*)&Ps_h[(16 * wid + gid) * RSTRH + j * 8 + 2 * tig]     = h01;
                    *(__half2*)&Ps_h[(16 * wid + gid + 8) * RSTRH + j * 8 + 2 * tig] = h23;
                }
            } else {
#pragma unroll
                for (int j = 0; j < 8; j++) {
                    const int dj = d - 8 * j;          // warp-uniform
                    __half2 h01, h23;
                    if (dj >= 135 || dj <= -143) {     // block fully masked
                        h01 = __half2(__float2half_rn(0.f), __float2half_rn(0.f));
                        h23 = h01;
                    } else {
                        int col = kt0 + j * 8 + 2 * tig;
                        float e0 = (abs(r0g - col)     < WIN) ? __expf(sc[j][0] * SCALE) : 0.0f;
                        float e1 = (abs(r0g - col - 1) < WIN) ? __expf(sc[j][1] * SCALE) : 0.0f;
                        float e2 = (abs(r0g + 8 - col)     < WIN) ? __expf(sc[j][2] * SCALE) : 0.0f;
                        float e3 = (abs(r0g + 8 - col - 1) < WIN) ? __expf(sc[j][3] * SCALE) : 0.0f;
                        h01 = __floats2half2_rn(e0, e1);
                        h23 = __floats2half2_rn(e2, e3);
                        float2 f01 = __half22float2(h01);
                        float2 f23 = __half22float2(h23);
                        lp0 += f01.x + f01.y;
                        lp1 += f23.x + f23.y;
                    }
                    *(__half2*)&Ps_h[(16 * wid + gid) * RSTRH + j * 8 + 2 * tig]     = h01;
                    *(__half2*)&Ps_h[(16 * wid + gid + 8) * RSTRH + j * 8 + 2 * tig] = h23;
                }
            }
            __syncwarp();

            // ---- O += P V ----
#pragma unroll
            for (int ss = 0; ss < 4; ss++) {
                uint32_t ap[4], bf[8][2];
                LDM4(ap[0], ap[1], ap[2], ap[3], a_p + ss * 32);
#pragma unroll
                for (int jj = 0; jj < 4; jj++)
                    LDM4(bf[2*jj][0], bf[2*jj][1], bf[2*jj+1][0], bf[2*jj+1][1],
                         vbuf + jj * (16 * RSTRH * 2) + boff + ss * 32);
#pragma unroll
                for (int j = 0; j < 8; j++) mma_f16(o[j], ap, bf[j]);
            }
        }
        nb ^= 1;
    }

    lp0 += __shfl_xor_sync(0xffffffff, lp0, 1);
    lp0 += __shfl_xor_sync(0xffffffff, lp0, 2);
    lp1 += __shfl_xor_sync(0xffffffff, lp1, 1);
    lp1 += __shfl_xor_sync(0xffffffff, lp1, 2);
    const float inv0 = 1.0f / lp0;
    const float inv1 = 1.0f / lp1;

    __half* Og = g_ao + ((size_t)(b * SEQ + r0g)) * DIM + h * HDIM;
#pragma unroll
    for (int j = 0; j < 8; j++) {
        int c = j * 8 + 2 * tig;
        *(__half2*)(Og + c) = __floats2half2_rn(o[j][0] * inv0, o[j][1] * inv0);
        *(__half2*)(Og + (size_t)8 * DIM + c) = __floats2half2_rn(o[j][2] * inv1, o[j][3] * inv1);
    }
}

// ===========================================================================
extern "C" void kernel_launch(void* const* d_in, const int* in_sizes, int n_in,
                              void* d_out, int out_size) {
    const float* x  = (const float*)d_in[0];
    const float* Wq = (const float*)d_in[1];
    const float* Wk = (const float*)d_in[2];
    const float* Wv = (const float*)d_in[3];
    const float* Wo = (const float*)d_in[4];
    float* out = (float*)d_out;

    cudaFuncSetAttribute(gemm_qkv,
                         cudaFuncAttributeMaxDynamicSharedMemorySize, GEMM_SMEM_BYTES);
    cudaFuncSetAttribute(gemm_out,
                         cudaFuncAttributeMaxDynamicSharedMemorySize, GEMM_SMEM_BYTES);
    cudaFuncSetAttribute(attn_mma,
                         cudaFuncAttributeMaxDynamicSharedMemorySize, ATTN_SMEM_BYTES);

    // 0. Weight prep
    prep_w<<<dim3(32, 32, 4), dim3(32, 8)>>>(Wq, Wk, Wv, Wo);

    // 1. RoPE + x rounding (resets tile counter)
    rope_kernel<<<(NTOK * 512 + 255) / 256, 256>>>(x);

    // 2. Q,K,V projections — persistent, 296 CTAs (2/SM)
    gemm_qkv<<<296, 256, GEMM_SMEM_BYTES>>>();

    // 3. FP16 MMA windowed attention (double-buffered K/V)
    attn_mma<<<dim3(SEQ / 128, HEADS, BATCH), 256, ATTN_SMEM_BYTES>>>();

    // 4. Output projection -> d_out (fp32)
    gemm_out<<<dim3(8, 32), 256, GEMM_SMEM_BYTES>>>(out);
    (void)in_sizes; (void)n_in; (void)out_size;
}

// round 13
// speedup vs baseline: 2.8035x; 1.0276x over previous
#include <cuda_runtime.h>
#include <cuda_fp16.h>
#include <math.h>
#include <cstdint>

#define BATCH 2
#define SEQ   2048
#define NTOK  (BATCH*SEQ)      // 4096
#define DIM   1024
#define HEADS 16
#define HDIM  64
#define WIN   128
#define SCALE 0.125f           // 1/sqrt(64)

// Scratch (device globals; no allocation allowed)
__device__ __half g_qin[NTOK*DIM];    // rope output, fp16
__device__ __half g_xr [NTOK*DIM];    // x, fp16
__device__ __half g_q  [NTOK*DIM];    // Q fp16
__device__ __half g_k  [NTOK*DIM];    // K fp16
__device__ __half g_vt [NTOK*DIM];    // V^T fp16: [(b*16+h)*64+d][s]
__device__ __half g_ao [NTOK*DIM];    // attention out fp16
__device__ __half g_wr [4*DIM*DIM];   // W^T fp16: [mat][n][k]
__device__ unsigned int g_tctr;       // persistent-GEMM tile counter

#define CPA(dst, src) \
    asm volatile("cp.async.cg.shared.global [%0], [%1], 16;" :: "r"(dst), "l"(src) : "memory")
#define CPC() asm volatile("cp.async.commit_group;" ::: "memory")
#define CPW(n) asm volatile("cp.async.wait_group %0;" :: "n"(n) : "memory")
#define LDM4(r0, r1, r2, r3, a) \
    asm volatile("ldmatrix.sync.aligned.m8n8.x4.shared.b16 {%0,%1,%2,%3}, [%4];" \
        : "=r"(r0), "=r"(r1), "=r"(r2), "=r"(r3) : "r"(a))

__device__ __forceinline__ uint32_t smem_u32(const void* p) {
    uint32_t a;
    asm("{ .reg .u64 t; cvta.to.shared.u64 t, %1; cvt.u32.u64 %0, t; }" : "=r"(a) : "l"(p));
    return a;
}

__device__ __forceinline__ void mma_f16(float* c, const uint32_t* a, const uint32_t* b) {
    asm volatile(
        "mma.sync.aligned.m16n8k16.row.col.f32.f16.f16.f32 "
        "{%0,%1,%2,%3}, {%4,%5,%6,%7}, {%8,%9}, {%0,%1,%2,%3};"
        : "+f"(c[0]), "+f"(c[1]), "+f"(c[2]), "+f"(c[3])
        : "r"(a[0]), "r"(a[1]), "r"(a[2]), "r"(a[3]), "r"(b[0]), "r"(b[1]));
}

// ===========================================================================
// Merged prep: blocks [0,4096) transpose+round the 4 weight matrices;
// blocks [4096,12288) do RoPE + x rounding. One launch instead of two.
// ===========================================================================
__global__ void prep_all(const float* __restrict__ x,
                         const float* __restrict__ w0, const float* __restrict__ w1,
                         const float* __restrict__ w2, const float* __restrict__ w3) {
    if (blockIdx.x < 4096) {
        __shared__ float t[32][33];
        const int z   = blockIdx.x >> 10;
        const int rem = blockIdx.x & 1023;
        const int n0  = (rem & 31) * 32;
        const int k0  = (rem >> 5) * 32;
        const int tx  = threadIdx.x & 31;
        const int ty  = threadIdx.x >> 5;     // 0..7
        const float* w = (z == 0) ? w0 : (z == 1) ? w1 : (z == 2) ? w2 : w3;
        for (int r = ty; r < 32; r += 8)
            t[r][tx] = w[(size_t)(k0 + r) * DIM + n0 + tx];
        __syncthreads();
        __half* o = g_wr + (size_t)z * DIM * DIM;
        for (int r = ty; r < 32; r += 8)
            o[(size_t)(n0 + r) * DIM + k0 + tx] = __float2half_rn(t[tx][r]);
    } else {
        int idx = (blockIdx.x - 4096) * 256 + threadIdx.x;   // NTOK*512
        if (idx == 0) g_tctr = 0;
        int t   = idx >> 9;
        int rem = idx & 511;
        int h   = rem >> 5;
        int i   = rem & 31;
        int s   = t & (SEQ - 1);

        float inv = expf(-(float)i * (9.210340371976184f / 32.0f));
        float ang = (float)s * inv;
        float sn, cs;
        sincosf(ang, &sn, &cs);

        const float* xp = x     + (size_t)t * DIM + h * HDIM;
        __half*      qp = g_qin + (size_t)t * DIM + h * HDIM;
        __half*      xr = g_xr  + (size_t)t * DIM + h * HDIM;
        float x1 = xp[i];
        float x2 = xp[i + 32];
        qp[i]      = __float2half_rn(x1 * cs - x2 * sn);
        qp[i + 32] = __float2half_rn(x2 * cs + x1 * sn);
        xr[i]      = __float2half_rn(x1);
        xr[i + 32] = __float2half_rn(x2);
    }
}

// ===========================================================================
// FP16 GEMM (unchanged): CTA 128x128, 256 thr, warp tile 32x64, BK=64,
// 3-stage cp.async, ldmatrix; 110.6KB smem -> 2 CTAs/SM.
// ===========================================================================
#define RSTRH 72
#define A_BYTES (128 * RSTRH * 2)      // 18432
#define B_BYTES (128 * RSTRH * 2)      // 18432
#define SSZ     (A_BYTES + B_BYTES)    // 36864
#define GEMM_SMEM_BYTES (3 * SSZ)      // 110592
#define NCHUNK  (DIM / 64)             // 16

extern __shared__ uint32_t dsm[];

template <int MODE, typename OutT>
__device__ __forceinline__ void gemm_body(const __half* __restrict__ A,
                                          const __half* __restrict__ Wt,
                                          OutT* __restrict__ C,
                                          int row0, int col0) {
    const int tid  = threadIdx.x;
    const int wid  = tid >> 5;
    const int lane = tid & 31;
    const int gid  = lane >> 2;
    const int tig  = lane & 3;
    const int wm   = wid >> 1;
    const int wn   = wid & 1;
    const int mi   = lane >> 3;
    const int lr   = lane & 7;

    const uint32_t sb = smem_u32(dsm);

    const uint32_t a_lane = ((wm * 32 + (mi & 1) * 8 + lr) * RSTRH + (mi >> 1) * 8) * 2;
    const uint32_t b_lane = ((wn * 64 + (mi >> 1) * 8 + lr) * RSTRH + (mi & 1) * 8) * 2;

    float acc[2][8][4];
#pragma unroll
    for (int i = 0; i < 2; i++)
#pragma unroll
        for (int j = 0; j < 8; j++)
#pragma unroll
            for (int r = 0; r < 4; r++) acc[i][j][r] = 0.0f;

#define ISSUE_STAGE(s, c)                                                        \
    {                                                                            \
        uint32_t ab = sb + (s) * SSZ;                                            \
        uint32_t bb = ab + A_BYTES;                                              \
        _Pragma("unroll")                                                        \
        for (int it = 0; it < 4; it++) {                                         \
            int idx = it * 256 + tid;                                            \
            int m = idx >> 3, k8 = idx & 7;                                      \
            CPA(ab + m * 144 + k8 * 16,                                          \
                A + (size_t)(row0 + m) * DIM + (c) * 64 + k8 * 8);               \
            CPA(bb + m * 144 + k8 * 16,                                          \
                Wt + (size_t)(col0 + m) * DIM + (c) * 64 + k8 * 8);              \
        }                                                                        \
        CPC();                                                                   \
    }

    ISSUE_STAGE(0, 0);
    ISSUE_STAGE(1, 1);

    int s = 0;
    for (int c = 0; c < NCHUNK; c++) {
        CPW(1);
        __syncthreads();
        if (c + 2 < NCHUNK) {
            int sn = (s + 2 >= 3) ? s - 1 : s + 2;
            ISSUE_STAGE(sn, c + 2);
        }

        const uint32_t abase = sb + s * SSZ;
        const uint32_t bbase = abase + A_BYTES;
#pragma unroll
        for (int ss = 0; ss < 4; ss++) {
            const int ksf = ss * 32;
            uint32_t af[2][4], bf[8][2];
#pragma unroll
            for (int i = 0; i < 2; i++)
                LDM4(af[i][0], af[i][1], af[i][2], af[i][3],
                     abase + a_lane + i * (16 * RSTRH * 2) + ksf);
#pragma unroll
            for (int jj = 0; jj < 4; jj++)
                LDM4(bf[2 * jj][0], bf[2 * jj][1], bf[2 * jj + 1][0], bf[2 * jj + 1][1],
                     bbase + b_lane + jj * (16 * RSTRH * 2) + ksf);
#pragma unroll
            for (int i = 0; i < 2; i++)
#pragma unroll
                for (int j = 0; j < 8; j++)
                    mma_f16(acc[i][j], af[i], bf[j]);
        }
        s = (s + 1 == 3) ? 0 : s + 1;
    }

#pragma unroll
    for (int i = 0; i < 2; i++) {
        int r0 = row0 + wm * 32 + i * 16 + gid;
#pragma unroll
        for (int j = 0; j < 8; j++) {
            int cc = col0 + wn * 64 + j * 8 + tig * 2;
            if (MODE == 0) {
                float* Cf = (float*)C;
                *(float2*)(Cf + (size_t)r0 * DIM + cc)       = make_float2(acc[i][j][0], acc[i][j][1]);
                *(float2*)(Cf + (size_t)(r0 + 8) * DIM + cc) = make_float2(acc[i][j][2], acc[i][j][3]);
            } else if (MODE == 1) {
                __half* Ch = (__half*)C;
                *(__half2*)(Ch + (size_t)r0 * DIM + cc) =
                    __floats2half2_rn(acc[i][j][0], acc[i][j][1]);
                *(__half2*)(Ch + (size_t)(r0 + 8) * DIM + cc) =
                    __floats2half2_rn(acc[i][j][2], acc[i][j][3]);
            } else {
                __half* Ch = (__half*)C;
                int b0 = r0 >> 11, s0 = r0 & 2047;
                int hh = cc >> 6,  dd = cc & 63;
                __half* base = Ch + ((size_t)(b0 * HEADS + hh) * HDIM) * SEQ;
                base[(size_t)(dd)     * SEQ + s0] = __float2half_rn(acc[i][j][0]);
                base[(size_t)(dd + 1) * SEQ + s0] = __float2half_rn(acc[i][j][1]);
                int r1 = r0 + 8;
                int b1 = r1 >> 11, s1 = r1 & 2047;
                __half* base1 = Ch + ((size_t)(b1 * HEADS + hh) * HDIM) * SEQ;
                base1[(size_t)(dd)     * SEQ + s1] = __float2half_rn(acc[i][j][2]);
                base1[(size_t)(dd + 1) * SEQ + s1] = __float2half_rn(acc[i][j][3]);
            }
        }
    }
}

#define QKV_TILES 768

__global__ __launch_bounds__(256, 2)
void gemm_qkv() {
    __shared__ unsigned int s_tile;
    for (;;) {
        __syncthreads();
        if (threadIdx.x == 0) s_tile = atomicAdd(&g_tctr, 1u);
        __syncthreads();
        unsigned int tile = s_tile;
        if (tile >= QKV_TILES) return;

        const int mi   = tile >> 8;
        const int rem  = tile & 255;
        const int row0 = (rem >> 3) * 128;
        const int col0 = (rem & 7) * 128;
        const __half* Wt = g_wr + (size_t)mi * DIM * DIM;
        if (mi == 0)      gemm_body<1>(g_qin, Wt, g_q,  row0, col0);
        else if (mi == 1) gemm_body<1>(g_qin, Wt, g_k,  row0, col0);
        else              gemm_body<2>(g_xr,  Wt, g_vt, row0, col0);
    }
}

__global__ __launch_bounds__(256, 2)
void gemm_out(float* __restrict__ out) {
    gemm_body<0>(g_ao, g_wr + (size_t)3 * DIM * DIM, out, blockIdx.y * 128, blockIdx.x * 128);
}

// ===========================================================================
// FP16 MMA attention v3: double-buffered K/V, warp-uniform mask special-
// ization, S computed in two j-halves (sc[4][4] live -> ~75 regs -> 3 CTAs/SM)
// smem halves: Q[128*72] | K0|V0|K1|V1 [64*72 each] | P[128*72]  = 73728 B
// ===========================================================================
#define KVSZ (64 * RSTRH * 2)          // 9216 B
#define ATTN_SMEM_BYTES (128*RSTRH*2 + 4*KVSZ + 128*RSTRH*2)  // 73728

__global__ __launch_bounds__(256, 3)
void attn_mma() {
    extern __shared__ __half afh[];

    const int tid  = threadIdx.x;
    const int wid  = tid >> 5;
    const int lane = tid & 31;
    const int gid  = lane >> 2;
    const int tig  = lane & 3;
    const int mi   = lane >> 3;
    const int lr   = lane & 7;

    const int qt = blockIdx.x, h = blockIdx.y, b = blockIdx.z;
    const int q0 = qt * 128;

    const uint32_t sb = smem_u32(afh);
    const uint32_t Qb = sb;
    const uint32_t KV0 = sb + 128 * RSTRH * 2;
    const uint32_t Pb  = KV0 + 4 * KVSZ;
    __half* Ps_h = afh + 128 * RSTRH + 4 * 64 * RSTRH;

    const __half* Qg = g_q + ((size_t)(b * SEQ + q0)) * DIM + h * HDIM;
#pragma unroll
    for (int it = 0; it < 4; it++) {
        int idx = it * 256 + tid;
        int r = idx >> 3, c8 = idx & 7;
        CPA(Qb + r * 144 + c8 * 16, Qg + (size_t)r * DIM + c8 * 8);
    }
    CPC();

    const __half* Kgb = g_k  + ((size_t)(b * SEQ)) * DIM + h * HDIM;
    const __half* Vgb = g_vt + ((size_t)((b * HEADS + h) * HDIM)) * SEQ;

#define ISSUE_KV(kt0, nb)                                                        \
    {                                                                            \
        uint32_t kb = KV0 + (nb) * 2 * KVSZ;                                     \
        uint32_t vb = kb + KVSZ;                                                 \
        const __half* Kg = Kgb + (size_t)(kt0) * DIM;                            \
        const __half* Vg = Vgb + (kt0);                                          \
        _Pragma("unroll")                                                        \
        for (int it = 0; it < 2; it++) {                                         \
            int idx = it * 256 + tid;                                            \
            int r = idx >> 3, c8 = idx & 7;                                      \
            CPA(kb + r * 144 + c8 * 16, Kg + (size_t)r * DIM + c8 * 8);          \
            CPA(vb + r * 144 + c8 * 16, Vg + (size_t)r * SEQ + c8 * 8);          \
        }                                                                        \
        CPC();                                                                   \
    }

    const uint32_t a_q = Qb + ((16 * wid + (mi & 1) * 8 + lr) * RSTRH + (mi >> 1) * 8) * 2;
    const uint32_t a_p = Pb + ((16 * wid + (mi & 1) * 8 + lr) * RSTRH + (mi >> 1) * 8) * 2;
    const uint32_t boff = ((mi >> 1) * 8 + lr) * 144 + (mi & 1) * 16;

    float o[8][4];
#pragma unroll
    for (int j = 0; j < 8; j++)
#pragma unroll
        for (int r = 0; r < 4; r++) o[j][r] = 0.0f;
    float lp0 = 0.0f, lp1 = 0.0f;
    const int r0g = q0 + 16 * wid + gid;

    const int p_lo = (q0 == 0) ? 2 : 0;
    const int p_hi = min(5, (SEQ + 64 - q0) / 64);

    ISSUE_KV(q0 - 128 + p_lo * 64, 0);

    int nb = 0;
    for (int p = p_lo; p <= p_hi; p++) {
        const int kt0 = q0 - 128 + p * 64;

        __syncthreads();
        if (p < p_hi) { ISSUE_KV(kt0 + 64, nb ^ 1); CPW(1); }
        else CPW(0);
        __syncthreads();

        const int d = q0 + 16 * wid - kt0;     // warp-uniform
        if (d > -143 && d < 191) {
            const uint32_t kbuf = KV0 + nb * 2 * KVSZ;
            const uint32_t vbuf = kbuf + KVSZ;
            const bool full = (d >= -64) && (d <= 112);

            // ---- S = Q K^T in two j-halves; mask+exp+P per half ----
#pragma unroll
            for (int jh = 0; jh < 2; jh++) {
                float sc[4][4];
#pragma unroll
                for (int j = 0; j < 4; j++)
#pragma unroll
                    for (int r = 0; r < 4; r++) sc[j][r] = 0.0f;
#pragma unroll
                for (int ss = 0; ss < 4; ss++) {
                    uint32_t aq[4], bf[4][2];
                    LDM4(aq[0], aq[1], aq[2], aq[3], a_q + ss * 32);
#pragma unroll
                    for (int jj = 0; jj < 2; jj++)
                        LDM4(bf[2*jj][0], bf[2*jj][1], bf[2*jj+1][0], bf[2*jj+1][1],
                             kbuf + (jh * 2 + jj) * (16 * RSTRH * 2) + boff + ss * 32);
#pragma unroll
                    for (int j = 0; j < 4; j++) mma_f16(sc[j], aq, bf[j]);
                }

#pragma unroll
                for (int j = 0; j < 4; j++) {
                    const int jg = jh * 4 + j;
                    __half2 h01, h23;
                    if (full) {
                        float e0 = __expf(sc[j][0] * SCALE);
                        float e1 = __expf(sc[j][1] * SCALE);
                        float e2 = __expf(sc[j][2] * SCALE);
                        float e3 = __expf(sc[j][3] * SCALE);
                        lp0 += e0 + e1;
                        lp1 += e2 + e3;
                        h01 = __floats2half2_rn(e0, e1);
                        h23 = __floats2half2_rn(e2, e3);
                    } else {
                        const int dj = d - 8 * jg;         // warp-uniform
                        if (dj >= 135 || dj <= -143) {
                            h01 = __half2(__float2half_rn(0.f), __float2half_rn(0.f));
                            h23 = h01;
                        } else {
                            int col = kt0 + jg * 8 + 2 * tig;
                            float e0 = (abs(r0g - col)     < WIN) ? __expf(sc[j][0] * SCALE) : 0.0f;
                            float e1 = (abs(r0g - col - 1) < WIN) ? __expf(sc[j][1] * SCALE) : 0.0f;
                            float e2 = (abs(r0g + 8 - col)     < WIN) ? __expf(sc[j][2] * SCALE) : 0.0f;
                            float e3 = (abs(r0g + 8 - col - 1) < WIN) ? __expf(sc[j][3] * SCALE) : 0.0f;
                            lp0 += e0 + e1;
                            lp1 += e2 + e3;
                            h01 = __floats2half2_rn(e0, e1);
                            h23 = __floats2half2_rn(e2, e3);
                        }
                    }
                    *(__half2*)&Ps_h[(16 * wid + gid) * RSTRH + jg * 8 + 2 * tig]     = h01;
                    *(__half2*)&Ps_h[(16 * wid + gid + 8) * RSTRH + jg * 8 + 2 * tig] = h23;
                }
            }
            __syncwarp();

            // ---- O += P V ----
#pragma unroll
            for (int ss = 0; ss < 4; ss++) {
                uint32_t ap[4], bf[8][2];
                LDM4(ap[0], ap[1], ap[2], ap[3], a_p + ss * 32);
#pragma unroll
                for (int jj = 0; jj < 4; jj++)
                    LDM4(bf[2*jj][0], bf[2*jj][1], bf[2*jj+1][0], bf[2*jj+1][1],
                         vbuf + jj * (16 * RSTRH * 2) + boff + ss * 32);
#pragma unroll
                for (int j = 0; j < 8; j++) mma_f16(o[j], ap, bf[j]);
            }
        }
        nb ^= 1;
    }

    lp0 += __shfl_xor_sync(0xffffffff, lp0, 1);
    lp0 += __shfl_xor_sync(0xffffffff, lp0, 2);
    lp1 += __shfl_xor_sync(0xffffffff, lp1, 1);
    lp1 += __shfl_xor_sync(0xffffffff, lp1, 2);
    const float inv0 = 1.0f / lp0;
    const float inv1 = 1.0f / lp1;

    __half* Og = g_ao + ((size_t)(b * SEQ + r0g)) * DIM + h * HDIM;
#pragma unroll
    for (int j = 0; j < 8; j++) {
        int c = j * 8 + 2 * tig;
        *(__half2*)(Og + c) = __floats2half2_rn(o[j][0] * inv0, o[j][1] * inv0);
        *(__half2*)(Og + (size_t)8 * DIM + c) = __floats2half2_rn(o[j][2] * inv1, o[j][3] * inv1);
    }
}

// ===========================================================================
extern "C" void kernel_launch(void* const* d_in, const int* in_sizes, int n_in,
                              void* d_out, int out_size) {
    const float* x  = (const float*)d_in[0];
    const float* Wq = (const float*)d_in[1];
    const float* Wk = (const float*)d_in[2];
    const float* Wv = (const float*)d_in[3];
    const float* Wo = (const float*)d_in[4];
    float* out = (float*)d_out;

    cudaFuncSetAttribute(gemm_qkv,
                         cudaFuncAttributeMaxDynamicSharedMemorySize, GEMM_SMEM_BYTES);
    cudaFuncSetAttribute(gemm_out,
                         cudaFuncAttributeMaxDynamicSharedMemorySize, GEMM_SMEM_BYTES);
    cudaFuncSetAttribute(attn_mma,
                         cudaFuncAttributeMaxDynamicSharedMemorySize, ATTN_SMEM_BYTES);

    // 0+1. Weight prep + RoPE + x rounding (one launch; resets tile counter)
    prep_all<<<12288, 256>>>(x, Wq, Wk, Wv, Wo);

    // 2. Q,K,V projections — persistent, 296 CTAs (2/SM)
    gemm_qkv<<<296, 256, GEMM_SMEM_BYTES>>>();

    // 3. FP16 MMA windowed attention (3 CTAs/SM)
    attn_mma<<<dim3(SEQ / 128, HEADS, BATCH), 256, ATTN_SMEM_BYTES>>>();

    // 4. Output projection -> d_out (fp32)
    gemm_out<<<dim3(8, 32), 256, GEMM_SMEM_BYTES>>>(out);
    (void)in_sizes; (void)n_in; (void)out_size;
}